// round 12
// baseline (speedup 1.0000x reference)
#include <cuda_runtime.h>
#include <cuda_fp16.h>
#include <cstdint>

#define NN 50000
#define FIN 128
#define HCC 256
#define EE 800000
#define BN_EPS 1e-5f
#define SCHUNK 1024
#define NBLK ((NN + SCHUNK - 1) / SCHUNK)   // 49

// ---------------- scratch (device globals; no allocation allowed) ----------------
__device__ __align__(16) float  d_Y1lin[(size_t)NN * 256];
__device__ __align__(16) __half d_HWh[(size_t)NN * 256];   // hW in fp16
__device__ __align__(16) float  d_h1[(size_t)NN * HCC];
__device__ __align__(16) float  d_als1[NN * 4];
__device__ __align__(16) float  d_ald1[NN * 4];
__device__ __align__(16) float  d_Y2[NN * 4];
__device__ float d_als2[NN];
__device__ float d_ald2[NN];
__device__ int   d_deg[NN];
__device__ int   d_rowptr[NN + 1];
__device__ int   d_wpos[NN];
__device__ int   d_ssrc[EE];
__device__ int   d_bsum[NBLK];
__device__ int   d_boff[NBLK];
__device__ float d_sum1[FIN], d_sq1[FIN];
__device__ float d_sum3[HCC], d_sq3[HCC];
__device__ __align__(16) float d_W1eff[FIN * 512];
__device__ float d_c1[512];
__device__ float d_W2effT[4 * HCC];
__device__ float d_c2[4];
__device__ int   d_is64;

// ---------------- helpers ----------------
__device__ __forceinline__ float warpSum(float v) {
    #pragma unroll
    for (int o = 16; o; o >>= 1) v += __shfl_xor_sync(0xffffffffu, v, o);
    return v;
}
__device__ __forceinline__ float lrelu(float x) { return x > 0.f ? x : 0.2f * x; }
__device__ __forceinline__ float sel4(float a, float b, float c, float d, int h) {
    return h < 2 ? (h == 0 ? a : b) : (h == 2 ? c : d);
}
__device__ __forceinline__ float expl(float e) { return __expf(fminf(e, 60.f)); }
__device__ __forceinline__ uint32_t f2tf(float x) {
    uint32_t r;
    asm("cvt.rna.tf32.f32 %0, %1;" : "=r"(r) : "f"(x));
    return r;
}
__device__ __forceinline__ void mma8(float* d, const uint32_t* a, const uint32_t* b) {
    asm volatile("mma.sync.aligned.m16n8k8.row.col.f32.tf32.tf32.f32 "
        "{%0,%1,%2,%3}, {%4,%5,%6,%7}, {%8,%9}, {%0,%1,%2,%3};"
        : "+f"(d[0]), "+f"(d[1]), "+f"(d[2]), "+f"(d[3])
        : "r"(a[0]), "r"(a[1]), "r"(a[2]), "r"(a[3]), "r"(b[0]), "r"(b[1]));
}

// ---------------- kernels ----------------
// side-stream init: degree histogram state
__global__ void k_zeroB() {
    int i = blockIdx.x * blockDim.x + threadIdx.x;
    if (i < NN) d_deg[i] = 0;
    if (i == 0) d_is64 = 1;
}
// main-stream init: BN stat accumulators
__global__ void k_zeroA() {
    int i = blockIdx.x * blockDim.x + threadIdx.x;
    if (i < FIN) { d_sum1[i] = 0.f; d_sq1[i] = 0.f; }
    if (i < HCC) { d_sum3[i] = 0.f; d_sq3[i] = 0.f; }
}

// sampling dtype probe: 4096 strided 8-byte words. int32-packed words look huge.
__global__ void k_detect(const long long* __restrict__ p) {
    int i = blockIdx.x * blockDim.x + threadIdx.x;     // 4096 threads
    long long v = p[(size_t)i * (EE / 4096)];
    if (v < 0 || v >= NN) d_is64 = 0;
}

// degree histogram reading edge_index directly
__global__ void k_hist(const void* __restrict__ ei) {
    bool is64 = (d_is64 != 0);
    int stride = gridDim.x * blockDim.x;
    for (int e = blockIdx.x * blockDim.x + threadIdx.x; e < EE; e += stride) {
        int d = is64 ? (int)((const long long*)ei)[EE + e] : ((const int*)ei)[EE + e];
        if (d >= 0 && d < NN) atomicAdd(&d_deg[d], 1);
    }
}

// ---- multi-block exclusive scan of d_deg -> d_rowptr/d_wpos ----
__global__ void k_blocksum() {                 // grid=NBLK, block=256
    __shared__ int sh[256];
    int b = blockIdx.x, t = threadIdx.x;
    int base = b * SCHUNK;
    int s = 0;
    #pragma unroll 4
    for (int i = t; i < SCHUNK; i += 256) {
        int idx = base + i;
        if (idx < NN) s += d_deg[idx];
    }
    sh[t] = s;
    __syncthreads();
    #pragma unroll
    for (int o = 128; o; o >>= 1) {
        if (t < o) sh[t] += sh[t + o];
        __syncthreads();
    }
    if (t == 0) d_bsum[b] = sh[0];
}

__global__ void k_scanb() {                    // 1 block, 64 threads
    __shared__ int sh[64];
    int t = threadIdx.x;
    int v = (t < NBLK) ? d_bsum[t] : 0;
    sh[t] = v;
    __syncthreads();
    #pragma unroll
    for (int o = 1; o < 64; o <<= 1) {
        int u = (t >= o) ? sh[t - o] : 0;
        __syncthreads();
        sh[t] += u;
        __syncthreads();
    }
    if (t < NBLK) d_boff[t] = sh[t] - v;       // exclusive offsets
    if (t == 63) d_rowptr[NN] = sh[63];
}

__global__ void k_fill() {                     // grid=NBLK, block=1024
    __shared__ int sh[1024];
    int b = blockIdx.x, t = threadIdx.x;
    int idx = b * SCHUNK + t;
    int v = (idx < NN) ? d_deg[idx] : 0;
    sh[t] = v;
    __syncthreads();
    #pragma unroll
    for (int o = 1; o < 1024; o <<= 1) {
        int u = (t >= o) ? sh[t - o] : 0;
        __syncthreads();
        sh[t] += u;
        __syncthreads();
    }
    if (idx < NN) {
        int excl = sh[t] - v + d_boff[b];
        d_rowptr[idx] = excl;
        d_wpos[idx] = excl;
    }
}

__global__ void k_scatter(const void* __restrict__ ei) {
    bool is64 = (d_is64 != 0);
    int stride = gridDim.x * blockDim.x;
    for (int e = blockIdx.x * blockDim.x + threadIdx.x; e < EE; e += stride) {
        int d, s;
        if (is64) {
            d = (int)((const long long*)ei)[EE + e];
            s = (int)((const long long*)ei)[e];
        } else {
            d = ((const int*)ei)[EE + e];
            s = ((const int*)ei)[e];
        }
        if (d >= 0 && d < NN) {
            int p = atomicAdd(&d_wpos[d], 1);
            d_ssrc[p] = (s >= 0 && s < NN) ? s : 0;
        }
    }
}

__global__ void k_colstats_x(const float* __restrict__ X) {
    __shared__ float s_s[FIN], s_q[FIN];
    int tid = threadIdx.x;                     // 256
    if (tid < FIN) { s_s[tid] = 0.f; s_q[tid] = 0.f; }
    __syncthreads();
    int lane = tid & 31;
    int nw = (gridDim.x * blockDim.x) >> 5;
    int gw = (blockIdx.x * blockDim.x + tid) >> 5;
    float s0 = 0, s1 = 0, s2 = 0, s3 = 0, q0 = 0, q1 = 0, q2 = 0, q3 = 0;
    #pragma unroll 4
    for (int r = gw; r < NN; r += nw) {
        float4 v = *(const float4*)(X + (size_t)r * FIN + lane * 4);
        s0 += v.x; q0 += v.x * v.x;
        s1 += v.y; q1 += v.y * v.y;
        s2 += v.z; q2 += v.z * v.z;
        s3 += v.w; q3 += v.w * v.w;
    }
    atomicAdd(&s_s[lane * 4 + 0], s0); atomicAdd(&s_q[lane * 4 + 0], q0);
    atomicAdd(&s_s[lane * 4 + 1], s1); atomicAdd(&s_q[lane * 4 + 1], q1);
    atomicAdd(&s_s[lane * 4 + 2], s2); atomicAdd(&s_q[lane * 4 + 2], q2);
    atomicAdd(&s_s[lane * 4 + 3], s3); atomicAdd(&s_q[lane * 4 + 3], q3);
    __syncthreads();
    if (tid < FIN) { atomicAdd(&d_sum1[tid], s_s[tid]); atomicAdd(&d_sq1[tid], s_q[tid]); }
}

__global__ void k_colstats_h1() {
    __shared__ float s_s[HCC], s_q[HCC];
    int tid = threadIdx.x;                     // 256
    s_s[tid] = 0.f; s_q[tid] = 0.f;
    __syncthreads();
    int lane = tid & 31;
    int nw = (gridDim.x * blockDim.x) >> 5;
    int gw = (blockIdx.x * blockDim.x + tid) >> 5;
    float s[8] = {0, 0, 0, 0, 0, 0, 0, 0}, q[8] = {0, 0, 0, 0, 0, 0, 0, 0};
    #pragma unroll 4
    for (int r = gw; r < NN; r += nw) {
        const float* row = d_h1 + (size_t)r * HCC;
        float4 v0 = *(const float4*)(row + lane * 4);
        float4 v1 = *(const float4*)(row + 128 + lane * 4);
        s[0] += v0.x; q[0] += v0.x * v0.x; s[1] += v0.y; q[1] += v0.y * v0.y;
        s[2] += v0.z; q[2] += v0.z * v0.z; s[3] += v0.w; q[3] += v0.w * v0.w;
        s[4] += v1.x; q[4] += v1.x * v1.x; s[5] += v1.y; q[5] += v1.y * v1.y;
        s[6] += v1.z; q[6] += v1.z * v1.z; s[7] += v1.w; q[7] += v1.w * v1.w;
    }
    #pragma unroll
    for (int i = 0; i < 4; i++) {
        atomicAdd(&s_s[lane * 4 + i], s[i]);       atomicAdd(&s_q[lane * 4 + i], q[i]);
        atomicAdd(&s_s[128 + lane * 4 + i], s[4 + i]); atomicAdd(&s_q[128 + lane * 4 + i], q[4 + i]);
    }
    __syncthreads();
    atomicAdd(&d_sum3[tid], s_s[tid]); atomicAdd(&d_sq3[tid], s_q[tid]);
}

__global__ void k_fold1(const float* __restrict__ g, const float* __restrict__ b,
                        const float* __restrict__ lin1W, const float* __restrict__ lin1b,
                        const float* __restrict__ g1W) {
    __shared__ float ssc[FIN], tsh[FIN];
    int tid = threadIdx.x;                    // 512
    if (tid < FIN) {
        float mu  = d_sum1[tid] * (1.f / NN);
        float var = d_sq1[tid] * (1.f / NN) - mu * mu;
        float sc  = rsqrtf(var + BN_EPS) * g[tid];
        ssc[tid] = sc;
        tsh[tid] = b[tid] - mu * sc;
    }
    __syncthreads();
    int j = tid;
    float acc = (j < 256) ? lin1b[j] : 0.f;
    for (int k = 0; k < FIN; k++) {
        float w = (j < 256) ? lin1W[k * 256 + j] : g1W[k * 256 + (j - 256)];
        acc += tsh[k] * w;
    }
    d_c1[j] = acc;
    for (int idx = tid; idx < FIN * 512; idx += 512) {
        int k = idx >> 9, jj = idx & 511;
        float w = (jj < 256) ? lin1W[k * 256 + jj] : g1W[k * 256 + (jj - 256)];
        d_W1eff[idx] = ssc[k] * w;
    }
}

// Y1 = x @ W1eff + c1 via split-tf32 tensor-core MMA.
// lin cols -> d_Y1lin fp32 ; HW cols -> d_HWh fp16.
__global__ void __launch_bounds__(256) k_gemm1(const float* __restrict__ A) {
    __shared__ float As[128][36];
    __shared__ float Bs[32][128];
    int tid = threadIdx.x;
    int wid = tid >> 5, lane = tid & 31;
    int warpM = wid >> 2, warpN = wid & 3;
    int row0 = blockIdx.y * 128, col0 = blockIdx.x * 128;
    int rql = lane >> 2, kq = lane & 3;

    float acc[4][4][4];
    #pragma unroll
    for (int mi = 0; mi < 4; mi++)
        #pragma unroll
        for (int ni = 0; ni < 4; ni++)
            #pragma unroll
            for (int j = 0; j < 4; j++) acc[mi][ni][j] = 0.f;

    for (int kc = 0; kc < 4; kc++) {
        int kbase = kc * 32;
        #pragma unroll
        for (int i = 0; i < 4; i++) {
            int f = tid + i * 256;
            int r = f >> 3, q = (f & 7) * 4;
            int gr = row0 + r;
            float4 v = make_float4(0.f, 0.f, 0.f, 0.f);
            if (gr < NN) v = *(const float4*)(A + (size_t)gr * FIN + kbase + q);
            *(float4*)(&As[r][q]) = v;
        }
        #pragma unroll
        for (int i = 0; i < 4; i++) {
            int f = tid + i * 256;
            int kr = f >> 5, c = (f & 31) * 4;
            *(float4*)(&Bs[kr][c]) = *(const float4*)(d_W1eff + (size_t)(kbase + kr) * 512 + col0 + c);
        }
        __syncthreads();

        #pragma unroll
        for (int ks = 0; ks < 4; ks++) {
            int kb = ks * 8;
            uint32_t Ah[4][4], Al[4][4];
            #pragma unroll
            for (int mi = 0; mi < 4; mi++) {
                int r = warpM * 64 + mi * 16 + rql;
                float x0 = As[r][kb + kq];
                float x1 = As[r + 8][kb + kq];
                float x2 = As[r][kb + kq + 4];
                float x3 = As[r + 8][kb + kq + 4];
                Ah[mi][0] = f2tf(x0); Al[mi][0] = f2tf(x0 - __uint_as_float(Ah[mi][0]));
                Ah[mi][1] = f2tf(x1); Al[mi][1] = f2tf(x1 - __uint_as_float(Ah[mi][1]));
                Ah[mi][2] = f2tf(x2); Al[mi][2] = f2tf(x2 - __uint_as_float(Ah[mi][2]));
                Ah[mi][3] = f2tf(x3); Al[mi][3] = f2tf(x3 - __uint_as_float(Ah[mi][3]));
            }
            uint32_t Bh[4][2], Bl[4][2];
            #pragma unroll
            for (int ni = 0; ni < 4; ni++) {
                int c = warpN * 32 + ni * 8 + rql;
                float y0 = Bs[kb + kq][c];
                float y1 = Bs[kb + kq + 4][c];
                Bh[ni][0] = f2tf(y0); Bl[ni][0] = f2tf(y0 - __uint_as_float(Bh[ni][0]));
                Bh[ni][1] = f2tf(y1); Bl[ni][1] = f2tf(y1 - __uint_as_float(Bh[ni][1]));
            }
            #pragma unroll
            for (int mi = 0; mi < 4; mi++)
                #pragma unroll
                for (int ni = 0; ni < 4; ni++) {
                    mma8(acc[mi][ni], Al[mi], Bh[ni]);
                    mma8(acc[mi][ni], Ah[mi], Bl[ni]);
                    mma8(acc[mi][ni], Ah[mi], Bh[ni]);
                }
        }
        __syncthreads();
    }

    // epilogue
    bool isHW = (col0 >= 256);
    int cbase = isHW ? (col0 - 256) : col0;
    int cq = (lane & 3) * 2;
    float2 bias[4];
    #pragma unroll
    for (int ni = 0; ni < 4; ni++) {
        int gc = col0 + warpN * 32 + ni * 8 + cq;
        bias[ni] = make_float2(d_c1[gc], d_c1[gc + 1]);
    }
    #pragma unroll
    for (int mi = 0; mi < 4; mi++) {
        int rr = row0 + warpM * 64 + mi * 16 + rql;
        #pragma unroll
        for (int ni = 0; ni < 4; ni++) {
            int cc = cbase + warpN * 32 + ni * 8 + cq;
            float v0 = acc[mi][ni][0] + bias[ni].x;
            float v1 = acc[mi][ni][1] + bias[ni].y;
            float v2 = acc[mi][ni][2] + bias[ni].x;
            float v3 = acc[mi][ni][3] + bias[ni].y;
            if (isHW) {
                if (rr < NN)
                    *(__half2*)(d_HWh + (size_t)rr * 256 + cc) = __floats2half2_rn(v0, v1);
                if (rr + 8 < NN)
                    *(__half2*)(d_HWh + (size_t)(rr + 8) * 256 + cc) = __floats2half2_rn(v2, v3);
            } else {
                if (rr < NN)
                    *(float2*)(d_Y1lin + (size_t)rr * 256 + cc) = make_float2(v0, v1);
                if (rr + 8 < NN)
                    *(float2*)(d_Y1lin + (size_t)(rr + 8) * 256 + cc) = make_float2(v2, v3);
            }
        }
    }
}

// attention logit projections from fp16 hW
__global__ void k_alphas1(const float* __restrict__ asrc, const float* __restrict__ adst) {
    int w = (blockIdx.x * blockDim.x + threadIdx.x) >> 5;
    int lane = threadIdx.x & 31;
    if (w >= NN) return;
    uint4 pv = *(const uint4*)(d_HWh + (size_t)w * 256 + lane * 8);
    float2 f0 = __half22float2(*(__half2*)&pv.x);
    float2 f1 = __half22float2(*(__half2*)&pv.y);
    float2 f2 = __half22float2(*(__half2*)&pv.z);
    float2 f3 = __half22float2(*(__half2*)&pv.w);
    float4 a0 = *(const float4*)(asrc + lane * 8);
    float4 a1 = *(const float4*)(asrc + lane * 8 + 4);
    float4 b0 = *(const float4*)(adst + lane * 8);
    float4 b1 = *(const float4*)(adst + lane * 8 + 4);
    float s = f0.x * a0.x + f0.y * a0.y + f1.x * a0.z + f1.y * a0.w
            + f2.x * a1.x + f2.y * a1.y + f3.x * a1.z + f3.y * a1.w;
    float d = f0.x * b0.x + f0.y * b0.y + f1.x * b0.z + f1.y * b0.w
            + f2.x * b1.x + f2.y * b1.y + f3.x * b1.z + f3.y * b1.w;
    #pragma unroll
    for (int o = 1; o < 8; o <<= 1) {
        s += __shfl_xor_sync(0xffffffffu, s, o);
        d += __shfl_xor_sync(0xffffffffu, d, o);
    }
    if ((lane & 7) == 0) {
        d_als1[w * 4 + (lane >> 3)] = s;
        d_ald1[w * 4 + (lane >> 3)] = d;
    }
}

// layer-1 edge aggregation (max-free softmax) + combine + relu -> h1. One warp per dst node.
__global__ void k_edge1(const float* __restrict__ g1bias) {
    int w = (blockIdx.x * blockDim.x + threadIdx.x) >> 5;
    int lane = threadIdx.x & 31;
    if (w >= NN) return;
    int beg = d_rowptr[w], end = d_rowptr[w + 1];
    int h = lane >> 3;
    float acc[8];
    #pragma unroll
    for (int j = 0; j < 8; j++) acc[j] = 0.f;

    if (end > beg) {
        float4 adv = *(const float4*)(d_ald1 + w * 4);
        float s0 = 0.f, s1 = 0.f, s2 = 0.f, s3 = 0.f;
        #pragma unroll 2
        for (int i = beg + lane; i < end; i += 32) {
            int s = d_ssrc[i];
            float4 avv = *(const float4*)(d_als1 + s * 4);
            s0 += expl(lrelu(avv.x + adv.x));
            s1 += expl(lrelu(avv.y + adv.y));
            s2 += expl(lrelu(avv.z + adv.z));
            s3 += expl(lrelu(avv.w + adv.w));
        }
        s0 = warpSum(s0); s1 = warpSum(s1); s2 = warpSum(s2); s3 = warpSum(s3);
        float adh  = sel4(adv.x, adv.y, adv.z, adv.w, h);
        float invh = 1.f / (sel4(s0, s1, s2, s3, h) + 1e-16f);
        #pragma unroll 4
        for (int i = beg; i < end; i++) {
            int s = d_ssrc[i];
            float avh = sel4(d_als1[s * 4 + 0], d_als1[s * 4 + 1],
                             d_als1[s * 4 + 2], d_als1[s * 4 + 3], h);
            float wgt = expl(lrelu(avh + adh)) * invh;
            uint4 pv = *(const uint4*)(d_HWh + (size_t)s * 256 + lane * 8);
            float2 f0 = __half22float2(*(__half2*)&pv.x);
            float2 f1 = __half22float2(*(__half2*)&pv.y);
            float2 f2 = __half22float2(*(__half2*)&pv.z);
            float2 f3 = __half22float2(*(__half2*)&pv.w);
            acc[0] += f0.x * wgt; acc[1] += f0.y * wgt;
            acc[2] += f1.x * wgt; acc[3] += f1.y * wgt;
            acc[4] += f2.x * wgt; acc[5] += f2.y * wgt;
            acc[6] += f3.x * wgt; acc[7] += f3.y * wgt;
        }
    }
    const float* linrow = d_Y1lin + (size_t)w * 256 + lane * 8;
    float4 l0 = *(const float4*)(linrow);
    float4 l1 = *(const float4*)(linrow + 4);
    float4 g0 = *(const float4*)(g1bias + lane * 8);
    float4 g1v = *(const float4*)(g1bias + lane * 8 + 4);
    float4 o0, o1;
    o0.x = fmaxf(acc[0] + l0.x + g0.x, 0.f);
    o0.y = fmaxf(acc[1] + l0.y + g0.y, 0.f);
    o0.z = fmaxf(acc[2] + l0.z + g0.z, 0.f);
    o0.w = fmaxf(acc[3] + l0.w + g0.w, 0.f);
    o1.x = fmaxf(acc[4] + l1.x + g1v.x, 0.f);
    o1.y = fmaxf(acc[5] + l1.y + g1v.y, 0.f);
    o1.z = fmaxf(acc[6] + l1.z + g1v.z, 0.f);
    o1.w = fmaxf(acc[7] + l1.w + g1v.w, 0.f);
    float* orow = d_h1 + (size_t)w * HCC + lane * 8;
    *(float4*)(orow) = o0;
    *(float4*)(orow + 4) = o1;
}

__global__ void k_fold2(const float* __restrict__ g, const float* __restrict__ b,
                        const float* __restrict__ lin3W, const float* __restrict__ lin3b,
                        const float* __restrict__ g2W) {
    __shared__ float ssc[HCC], tsh[HCC];
    int tid = threadIdx.x;                    // 256
    float mu  = d_sum3[tid] * (1.f / NN);
    float var = d_sq3[tid] * (1.f / NN) - mu * mu;
    float sc  = rsqrtf(var + BN_EPS) * g[tid];
    ssc[tid] = sc;
    tsh[tid] = b[tid] - mu * sc;
    __syncthreads();
    #pragma unroll
    for (int j = 0; j < 4; j++) {
        float w = (j < 2) ? lin3W[tid * 2 + j] : g2W[tid * 2 + (j - 2)];
        d_W2effT[j * HCC + tid] = ssc[tid] * w;
    }
    if (tid < 4) {
        float acc = (tid < 2) ? lin3b[tid] : 0.f;
        for (int k = 0; k < HCC; k++) {
            float w = (tid < 2) ? lin3W[k * 2 + tid] : g2W[k * 2 + (tid - 2)];
            acc += tsh[k] * w;
        }
        d_c2[tid] = acc;
    }
}

__global__ void k_gemm2(const float* __restrict__ asrc, const float* __restrict__ adst) {
    __shared__ float Wsh[4 * HCC];
    int tid = threadIdx.x;
    for (int i = tid; i < 4 * HCC; i += blockDim.x) Wsh[i] = d_W2effT[i];
    __syncthreads();
    int w = (blockIdx.x * blockDim.x + tid) >> 5;
    int lane = tid & 31;
    if (w >= NN) return;
    const float* hrow = d_h1 + (size_t)w * HCC;
    float a0 = 0.f, a1 = 0.f, a2 = 0.f, a3 = 0.f;
    #pragma unroll
    for (int j = 0; j < 8; j++) {
        int k = lane + 32 * j;
        float hv = hrow[k];
        a0 += hv * Wsh[k];
        a1 += hv * Wsh[HCC + k];
        a2 += hv * Wsh[2 * HCC + k];
        a3 += hv * Wsh[3 * HCC + k];
    }
    a0 = warpSum(a0); a1 = warpSum(a1); a2 = warpSum(a2); a3 = warpSum(a3);
    if (lane == 0) {
        a0 += d_c2[0]; a1 += d_c2[1]; a2 += d_c2[2]; a3 += d_c2[3];
        d_Y2[w * 4 + 0] = a0;
        d_Y2[w * 4 + 1] = a1;
        d_Y2[w * 4 + 2] = a2;
        d_Y2[w * 4 + 3] = a3;
        d_als2[w] = a2 * asrc[0] + a3 * asrc[1];
        d_ald2[w] = a2 * adst[0] + a3 * adst[1];
    }
}

__global__ void k_edge2(const float* __restrict__ g2bias, float* __restrict__ out) {
    int w = (blockIdx.x * blockDim.x + threadIdx.x) >> 5;
    int lane = threadIdx.x & 31;
    if (w >= NN) return;
    int beg = d_rowptr[w], end = d_rowptr[w + 1];
    float a0 = 0.f, a1 = 0.f;
    if (end > beg) {
        float ad = d_ald2[w];
        float ssum = 0.f;
        #pragma unroll 2
        for (int i = beg + lane; i < end; i += 32) {
            ssum += expl(lrelu(d_als2[d_ssrc[i]] + ad));
        }
        float inv = 1.f / (warpSum(ssum) + 1e-16f);
        #pragma unroll 2
        for (int i = beg + lane; i < end; i += 32) {
            int sv = d_ssrc[i];
            float wgt = expl(lrelu(d_als2[sv] + ad)) * inv;
            a0 += d_Y2[sv * 4 + 2] * wgt;
            a1 += d_Y2[sv * 4 + 3] * wgt;
        }
        a0 = warpSum(a0);
        a1 = warpSum(a1);
    }
    if (lane == 0) {
        float v0 = d_Y2[w * 4 + 0] + g2bias[0] + a0;
        float v1 = d_Y2[w * 4 + 1] + g2bias[1] + a1;
        out[w * 2 + 0] = v0 > 0.f ? v0 : 0.f;
        out[w * 2 + 1] = v1 > 0.f ? v1 : 0.f;
    }
}

// ---------------- launch ----------------
// Side stream + events for graph fork/join. Created lazily on the FIRST call
// (the uncaptured correctness run) because stream/event creation is illegal
// during an active global capture. Work recorded per call is identical, so
// kernel_launch remains deterministic.
static cudaStream_t g_s1 = 0;
static cudaEvent_t  g_eFork = 0, g_eJoin = 0;

extern "C" void kernel_launch(void* const* d_in, const int* in_sizes, int n_in,
                              void* d_out, int out_size) {
    const float* x       = (const float*)d_in[0];
    const void*  ei      = (const void*)d_in[1];
    const float* bn1_g   = (const float*)d_in[2];
    const float* bn1_b   = (const float*)d_in[3];
    const float* bn3_g   = (const float*)d_in[4];
    const float* bn3_b   = (const float*)d_in[5];
    const float* lin1_W  = (const float*)d_in[6];
    const float* lin1_b  = (const float*)d_in[7];
    const float* lin3_W  = (const float*)d_in[8];
    const float* lin3_b  = (const float*)d_in[9];
    const float* g1_W    = (const float*)d_in[10];
    const float* g1_asrc = (const float*)d_in[11];
    const float* g1_adst = (const float*)d_in[12];
    const float* g1_bias = (const float*)d_in[13];
    const float* g2_W    = (const float*)d_in[14];
    const float* g2_asrc = (const float*)d_in[15];
    const float* g2_adst = (const float*)d_in[16];
    const float* g2_bias = (const float*)d_in[17];
    float* out = (float*)d_out;

    if (g_s1 == 0) {
        cudaStreamCreateWithFlags(&g_s1, cudaStreamNonBlocking);
        cudaEventCreateWithFlags(&g_eFork, cudaEventDisableTiming);
        cudaEventCreateWithFlags(&g_eJoin, cudaEventDisableTiming);
    }

    const int warpsGrid = (NN * 32 + 255) / 256;   // 6250 blocks (warp/node)

    // fork at t=0
    cudaEventRecord(g_eFork, 0);
    cudaStreamWaitEvent(g_s1, g_eFork, 0);

    // chain B (graph build) on side stream — overlaps with chain A
    k_zeroB<<<(NN + 255) / 256, 256, 0, g_s1>>>();
    k_detect<<<16, 256, 0, g_s1>>>((const long long*)ei);
    k_hist<<<784, 256, 0, g_s1>>>(ei);
    k_blocksum<<<NBLK, 256, 0, g_s1>>>();
    k_scanb<<<1, 64, 0, g_s1>>>();
    k_fill<<<NBLK, 1024, 0, g_s1>>>();
    k_scatter<<<784, 256, 0, g_s1>>>(ei);
    cudaEventRecord(g_eJoin, g_s1);

    // chain A (dense compute) on main stream
    k_zeroA<<<1, 256>>>();
    k_colstats_x<<<512, 256>>>(x);
    k_fold1<<<1, 512>>>(bn1_g, bn1_b, lin1_W, lin1_b, g1_W);
    dim3 g1grid(4, (NN + 127) / 128);
    k_gemm1<<<g1grid, 256>>>(x);
    k_alphas1<<<warpsGrid, 256>>>(g1_asrc, g1_adst);

    // join: edge1 needs CSR (chain B) + gemm1 outputs (chain A)
    cudaStreamWaitEvent(0, g_eJoin, 0);
    k_edge1<<<warpsGrid, 256>>>(g1_bias);
    k_colstats_h1<<<512, 256>>>();
    k_fold2<<<1, 256>>>(bn3_g, bn3_b, lin3_W, lin3_b, g2_W);
    k_gemm2<<<warpsGrid, 256>>>(g2_asrc, g2_adst);
    k_edge2<<<warpsGrid, 256>>>(g2_bias, out);
}

// round 13
// speedup vs baseline: 1.0008x; 1.0008x over previous
#include <cuda_runtime.h>
#include <cuda_fp16.h>
#include <cstdint>

#define NN 50000
#define FIN 128
#define HCC 256
#define EE 800000
#define BN_EPS 1e-5f
#define SCHUNK 1024
#define NBLK ((NN + SCHUNK - 1) / SCHUNK)   // 49

// ---------------- scratch (device globals; no allocation allowed) ----------------
__device__ __align__(16) float  d_Y1lin[(size_t)NN * 256];
__device__ __align__(16) __half d_HWh[(size_t)NN * 256];   // hW in fp16
__device__ __align__(16) float  d_h1[(size_t)NN * HCC];
__device__ __align__(16) float  d_als1[NN * 4];
__device__ __align__(16) float  d_ald1[NN * 4];
__device__ __align__(16) float  d_Y2[NN * 4];
__device__ float d_als2[NN];
__device__ float d_ald2[NN];
__device__ int   d_deg[NN];
__device__ int   d_rowptr[NN + 1];
__device__ int   d_wpos[NN];
__device__ int   d_ssrc[EE];
__device__ int   d_bsum[NBLK];
__device__ int   d_boff[NBLK];
__device__ float d_sum1[FIN], d_sq1[FIN];
__device__ float d_sum3[HCC], d_sq3[HCC];
__device__ __align__(16) float d_W1eff[FIN * 512];
__device__ float d_c1[512];
__device__ float d_W2effT[4 * HCC];
__device__ float d_c2[4];
__device__ int   d_is64;

// ---------------- helpers ----------------
__device__ __forceinline__ float warpSum(float v) {
    #pragma unroll
    for (int o = 16; o; o >>= 1) v += __shfl_xor_sync(0xffffffffu, v, o);
    return v;
}
__device__ __forceinline__ float lrelu(float x) { return x > 0.f ? x : 0.2f * x; }
__device__ __forceinline__ float sel4(float a, float b, float c, float d, int h) {
    return h < 2 ? (h == 0 ? a : b) : (h == 2 ? c : d);
}
__device__ __forceinline__ float expl(float e) { return __expf(fminf(e, 60.f)); }
__device__ __forceinline__ uint32_t f2tf(float x) {
    uint32_t r;
    asm("cvt.rna.tf32.f32 %0, %1;" : "=r"(r) : "f"(x));
    return r;
}
__device__ __forceinline__ void mma8(float* d, const uint32_t* a, const uint32_t* b) {
    asm volatile("mma.sync.aligned.m16n8k8.row.col.f32.tf32.tf32.f32 "
        "{%0,%1,%2,%3}, {%4,%5,%6,%7}, {%8,%9}, {%0,%1,%2,%3};"
        : "+f"(d[0]), "+f"(d[1]), "+f"(d[2]), "+f"(d[3])
        : "r"(a[0]), "r"(a[1]), "r"(a[2]), "r"(a[3]), "r"(b[0]), "r"(b[1]));
}

// ---------------- kernels ----------------
__global__ void k_zeroB() {
    int i = blockIdx.x * blockDim.x + threadIdx.x;
    if (i < NN) d_deg[i] = 0;
    if (i == 0) d_is64 = 1;
}
__global__ void k_zeroA() {
    int i = blockIdx.x * blockDim.x + threadIdx.x;
    if (i < FIN) { d_sum1[i] = 0.f; d_sq1[i] = 0.f; }
    if (i < HCC) { d_sum3[i] = 0.f; d_sq3[i] = 0.f; }
}

// sampling dtype probe: 4096 strided 8-byte words. int32-packed words look huge.
__global__ void k_detect(const long long* __restrict__ p) {
    int i = blockIdx.x * blockDim.x + threadIdx.x;     // 4096 threads
    long long v = p[(size_t)i * (EE / 4096)];
    if (v < 0 || v >= NN) d_is64 = 0;
}

__global__ void k_hist(const void* __restrict__ ei) {
    bool is64 = (d_is64 != 0);
    int stride = gridDim.x * blockDim.x;
    for (int e = blockIdx.x * blockDim.x + threadIdx.x; e < EE; e += stride) {
        int d = is64 ? (int)((const long long*)ei)[EE + e] : ((const int*)ei)[EE + e];
        if (d >= 0 && d < NN) atomicAdd(&d_deg[d], 1);
    }
}

// ---- multi-block exclusive scan of d_deg -> d_rowptr/d_wpos ----
__global__ void k_blocksum() {                 // grid=NBLK, block=256
    __shared__ int sh[256];
    int b = blockIdx.x, t = threadIdx.x;
    int base = b * SCHUNK;
    int s = 0;
    #pragma unroll 4
    for (int i = t; i < SCHUNK; i += 256) {
        int idx = base + i;
        if (idx < NN) s += d_deg[idx];
    }
    sh[t] = s;
    __syncthreads();
    #pragma unroll
    for (int o = 128; o; o >>= 1) {
        if (t < o) sh[t] += sh[t + o];
        __syncthreads();
    }
    if (t == 0) d_bsum[b] = sh[0];
}

__global__ void k_scanb() {                    // 1 block, 64 threads
    __shared__ int sh[64];
    int t = threadIdx.x;
    int v = (t < NBLK) ? d_bsum[t] : 0;
    sh[t] = v;
    __syncthreads();
    #pragma unroll
    for (int o = 1; o < 64; o <<= 1) {
        int u = (t >= o) ? sh[t - o] : 0;
        __syncthreads();
        sh[t] += u;
        __syncthreads();
    }
    if (t < NBLK) d_boff[t] = sh[t] - v;       // exclusive offsets
    if (t == 63) d_rowptr[NN] = sh[63];
}

__global__ void k_fill() {                     // grid=NBLK, block=1024
    __shared__ int sh[1024];
    int b = blockIdx.x, t = threadIdx.x;
    int idx = b * SCHUNK + t;
    int v = (idx < NN) ? d_deg[idx] : 0;
    sh[t] = v;
    __syncthreads();
    #pragma unroll
    for (int o = 1; o < 1024; o <<= 1) {
        int u = (t >= o) ? sh[t - o] : 0;
        __syncthreads();
        sh[t] += u;
        __syncthreads();
    }
    if (idx < NN) {
        int excl = sh[t] - v + d_boff[b];
        d_rowptr[idx] = excl;
        d_wpos[idx] = excl;
    }
}

__global__ void k_scatter(const void* __restrict__ ei) {
    bool is64 = (d_is64 != 0);
    int stride = gridDim.x * blockDim.x;
    for (int e = blockIdx.x * blockDim.x + threadIdx.x; e < EE; e += stride) {
        int d, s;
        if (is64) {
            d = (int)((const long long*)ei)[EE + e];
            s = (int)((const long long*)ei)[e];
        } else {
            d = ((const int*)ei)[EE + e];
            s = ((const int*)ei)[e];
        }
        if (d >= 0 && d < NN) {
            int p = atomicAdd(&d_wpos[d], 1);
            d_ssrc[p] = (s >= 0 && s < NN) ? s : 0;
        }
    }
}

__global__ void k_colstats_x(const float* __restrict__ X) {
    __shared__ float s_s[FIN], s_q[FIN];
    int tid = threadIdx.x;                     // 256
    if (tid < FIN) { s_s[tid] = 0.f; s_q[tid] = 0.f; }
    __syncthreads();
    int lane = tid & 31;
    int nw = (gridDim.x * blockDim.x) >> 5;
    int gw = (blockIdx.x * blockDim.x + tid) >> 5;
    float s0 = 0, s1 = 0, s2 = 0, s3 = 0, q0 = 0, q1 = 0, q2 = 0, q3 = 0;
    #pragma unroll 4
    for (int r = gw; r < NN; r += nw) {
        float4 v = *(const float4*)(X + (size_t)r * FIN + lane * 4);
        s0 += v.x; q0 += v.x * v.x;
        s1 += v.y; q1 += v.y * v.y;
        s2 += v.z; q2 += v.z * v.z;
        s3 += v.w; q3 += v.w * v.w;
    }
    atomicAdd(&s_s[lane * 4 + 0], s0); atomicAdd(&s_q[lane * 4 + 0], q0);
    atomicAdd(&s_s[lane * 4 + 1], s1); atomicAdd(&s_q[lane * 4 + 1], q1);
    atomicAdd(&s_s[lane * 4 + 2], s2); atomicAdd(&s_q[lane * 4 + 2], q2);
    atomicAdd(&s_s[lane * 4 + 3], s3); atomicAdd(&s_q[lane * 4 + 3], q3);
    __syncthreads();
    if (tid < FIN) { atomicAdd(&d_sum1[tid], s_s[tid]); atomicAdd(&d_sq1[tid], s_q[tid]); }
}

__global__ void k_colstats_h1() {
    __shared__ float s_s[HCC], s_q[HCC];
    int tid = threadIdx.x;                     // 256
    s_s[tid] = 0.f; s_q[tid] = 0.f;
    __syncthreads();
    int lane = tid & 31;
    int nw = (gridDim.x * blockDim.x) >> 5;
    int gw = (blockIdx.x * blockDim.x + tid) >> 5;
    float s[8] = {0, 0, 0, 0, 0, 0, 0, 0}, q[8] = {0, 0, 0, 0, 0, 0, 0, 0};
    #pragma unroll 4
    for (int r = gw; r < NN; r += nw) {
        const float* row = d_h1 + (size_t)r * HCC;
        float4 v0 = *(const float4*)(row + lane * 4);
        float4 v1 = *(const float4*)(row + 128 + lane * 4);
        s[0] += v0.x; q[0] += v0.x * v0.x; s[1] += v0.y; q[1] += v0.y * v0.y;
        s[2] += v0.z; q[2] += v0.z * v0.z; s[3] += v0.w; q[3] += v0.w * v0.w;
        s[4] += v1.x; q[4] += v1.x * v1.x; s[5] += v1.y; q[5] += v1.y * v1.y;
        s[6] += v1.z; q[6] += v1.z * v1.z; s[7] += v1.w; q[7] += v1.w * v1.w;
    }
    #pragma unroll
    for (int i = 0; i < 4; i++) {
        atomicAdd(&s_s[lane * 4 + i], s[i]);       atomicAdd(&s_q[lane * 4 + i], q[i]);
        atomicAdd(&s_s[128 + lane * 4 + i], s[4 + i]); atomicAdd(&s_q[128 + lane * 4 + i], q[4 + i]);
    }
    __syncthreads();
    atomicAdd(&d_sum3[tid], s_s[tid]); atomicAdd(&d_sq3[tid], s_q[tid]);
}

__global__ void k_fold1(const float* __restrict__ g, const float* __restrict__ b,
                        const float* __restrict__ lin1W, const float* __restrict__ lin1b,
                        const float* __restrict__ g1W) {
    __shared__ float ssc[FIN], tsh[FIN];
    int tid = threadIdx.x;                    // 512
    if (tid < FIN) {
        float mu  = d_sum1[tid] * (1.f / NN);
        float var = d_sq1[tid] * (1.f / NN) - mu * mu;
        float sc  = rsqrtf(var + BN_EPS) * g[tid];
        ssc[tid] = sc;
        tsh[tid] = b[tid] - mu * sc;
    }
    __syncthreads();
    int j = tid;
    float acc = (j < 256) ? lin1b[j] : 0.f;
    for (int k = 0; k < FIN; k++) {
        float w = (j < 256) ? lin1W[k * 256 + j] : g1W[k * 256 + (j - 256)];
        acc += tsh[k] * w;
    }
    d_c1[j] = acc;
    for (int idx = tid; idx < FIN * 512; idx += 512) {
        int k = idx >> 9, jj = idx & 511;
        float w = (jj < 256) ? lin1W[k * 256 + jj] : g1W[k * 256 + (jj - 256)];
        d_W1eff[idx] = ssc[k] * w;
    }
}

// Y1 = x @ W1eff + c1 via 2-term split-tf32 MMA (AhBh + AhBl).
// B's truncation is compensated; A's tf32 rounding (~2.8e-4 rms, ~fp16-storage
// scale) is accepted — calibrated against the fp16-HW dilution measurement.
__global__ void __launch_bounds__(256) k_gemm1(const float* __restrict__ A) {
    __shared__ float As[128][36];
    __shared__ float Bs[32][128];
    int tid = threadIdx.x;
    int wid = tid >> 5, lane = tid & 31;
    int warpM = wid >> 2, warpN = wid & 3;
    int row0 = blockIdx.y * 128, col0 = blockIdx.x * 128;
    int rql = lane >> 2, kq = lane & 3;

    float acc[4][4][4];
    #pragma unroll
    for (int mi = 0; mi < 4; mi++)
        #pragma unroll
        for (int ni = 0; ni < 4; ni++)
            #pragma unroll
            for (int j = 0; j < 4; j++) acc[mi][ni][j] = 0.f;

    for (int kc = 0; kc < 4; kc++) {
        int kbase = kc * 32;
        #pragma unroll
        for (int i = 0; i < 4; i++) {
            int f = tid + i * 256;
            int r = f >> 3, q = (f & 7) * 4;
            int gr = row0 + r;
            float4 v = make_float4(0.f, 0.f, 0.f, 0.f);
            if (gr < NN) v = *(const float4*)(A + (size_t)gr * FIN + kbase + q);
            *(float4*)(&As[r][q]) = v;
        }
        #pragma unroll
        for (int i = 0; i < 4; i++) {
            int f = tid + i * 256;
            int kr = f >> 5, c = (f & 31) * 4;
            *(float4*)(&Bs[kr][c]) = *(const float4*)(d_W1eff + (size_t)(kbase + kr) * 512 + col0 + c);
        }
        __syncthreads();

        #pragma unroll
        for (int ks = 0; ks < 4; ks++) {
            int kb = ks * 8;
            uint32_t Ah[4][4];
            #pragma unroll
            for (int mi = 0; mi < 4; mi++) {
                int r = warpM * 64 + mi * 16 + rql;
                Ah[mi][0] = f2tf(As[r][kb + kq]);
                Ah[mi][1] = f2tf(As[r + 8][kb + kq]);
                Ah[mi][2] = f2tf(As[r][kb + kq + 4]);
                Ah[mi][3] = f2tf(As[r + 8][kb + kq + 4]);
            }
            uint32_t Bh[4][2], Bl[4][2];
            #pragma unroll
            for (int ni = 0; ni < 4; ni++) {
                int c = warpN * 32 + ni * 8 + rql;
                float y0 = Bs[kb + kq][c];
                float y1 = Bs[kb + kq + 4][c];
                Bh[ni][0] = f2tf(y0); Bl[ni][0] = f2tf(y0 - __uint_as_float(Bh[ni][0]));
                Bh[ni][1] = f2tf(y1); Bl[ni][1] = f2tf(y1 - __uint_as_float(Bh[ni][1]));
            }
            #pragma unroll
            for (int mi = 0; mi < 4; mi++)
                #pragma unroll
                for (int ni = 0; ni < 4; ni++) {
                    mma8(acc[mi][ni], Ah[mi], Bl[ni]);
                    mma8(acc[mi][ni], Ah[mi], Bh[ni]);
                }
        }
        __syncthreads();
    }

    // epilogue
    bool isHW = (col0 >= 256);
    int cbase = isHW ? (col0 - 256) : col0;
    int cq = (lane & 3) * 2;
    float2 bias[4];
    #pragma unroll
    for (int ni = 0; ni < 4; ni++) {
        int gc = col0 + warpN * 32 + ni * 8 + cq;
        bias[ni] = make_float2(d_c1[gc], d_c1[gc + 1]);
    }
    #pragma unroll
    for (int mi = 0; mi < 4; mi++) {
        int rr = row0 + warpM * 64 + mi * 16 + rql;
        #pragma unroll
        for (int ni = 0; ni < 4; ni++) {
            int cc = cbase + warpN * 32 + ni * 8 + cq;
            float v0 = acc[mi][ni][0] + bias[ni].x;
            float v1 = acc[mi][ni][1] + bias[ni].y;
            float v2 = acc[mi][ni][2] + bias[ni].x;
            float v3 = acc[mi][ni][3] + bias[ni].y;
            if (isHW) {
                if (rr < NN)
                    *(__half2*)(d_HWh + (size_t)rr * 256 + cc) = __floats2half2_rn(v0, v1);
                if (rr + 8 < NN)
                    *(__half2*)(d_HWh + (size_t)(rr + 8) * 256 + cc) = __floats2half2_rn(v2, v3);
            } else {
                if (rr < NN)
                    *(float2*)(d_Y1lin + (size_t)rr * 256 + cc) = make_float2(v0, v1);
                if (rr + 8 < NN)
                    *(float2*)(d_Y1lin + (size_t)(rr + 8) * 256 + cc) = make_float2(v2, v3);
            }
        }
    }
}

// attention logit projections from fp16 hW
__global__ void k_alphas1(const float* __restrict__ asrc, const float* __restrict__ adst) {
    int w = (blockIdx.x * blockDim.x + threadIdx.x) >> 5;
    int lane = threadIdx.x & 31;
    if (w >= NN) return;
    uint4 pv = *(const uint4*)(d_HWh + (size_t)w * 256 + lane * 8);
    float2 f0 = __half22float2(*(__half2*)&pv.x);
    float2 f1 = __half22float2(*(__half2*)&pv.y);
    float2 f2 = __half22float2(*(__half2*)&pv.z);
    float2 f3 = __half22float2(*(__half2*)&pv.w);
    float4 a0 = *(const float4*)(asrc + lane * 8);
    float4 a1 = *(const float4*)(asrc + lane * 8 + 4);
    float4 b0 = *(const float4*)(adst + lane * 8);
    float4 b1 = *(const float4*)(adst + lane * 8 + 4);
    float s = f0.x * a0.x + f0.y * a0.y + f1.x * a0.z + f1.y * a0.w
            + f2.x * a1.x + f2.y * a1.y + f3.x * a1.z + f3.y * a1.w;
    float d = f0.x * b0.x + f0.y * b0.y + f1.x * b0.z + f1.y * b0.w
            + f2.x * b1.x + f2.y * b1.y + f3.x * b1.z + f3.y * b1.w;
    #pragma unroll
    for (int o = 1; o < 8; o <<= 1) {
        s += __shfl_xor_sync(0xffffffffu, s, o);
        d += __shfl_xor_sync(0xffffffffu, d, o);
    }
    if ((lane & 7) == 0) {
        d_als1[w * 4 + (lane >> 3)] = s;
        d_ald1[w * 4 + (lane >> 3)] = d;
    }
}

// layer-1 edge aggregation (max-free softmax) + combine + relu -> h1. One warp per dst node.
__global__ void k_edge1(const float* __restrict__ g1bias) {
    int w = (blockIdx.x * blockDim.x + threadIdx.x) >> 5;
    int lane = threadIdx.x & 31;
    if (w >= NN) return;
    int beg = d_rowptr[w], end = d_rowptr[w + 1];
    int h = lane >> 3;
    float acc[8];
    #pragma unroll
    for (int j = 0; j < 8; j++) acc[j] = 0.f;

    if (end > beg) {
        float4 adv = *(const float4*)(d_ald1 + w * 4);
        float s0 = 0.f, s1 = 0.f, s2 = 0.f, s3 = 0.f;
        #pragma unroll 2
        for (int i = beg + lane; i < end; i += 32) {
            int s = d_ssrc[i];
            float4 avv = *(const float4*)(d_als1 + s * 4);
            s0 += expl(lrelu(avv.x + adv.x));
            s1 += expl(lrelu(avv.y + adv.y));
            s2 += expl(lrelu(avv.z + adv.z));
            s3 += expl(lrelu(avv.w + adv.w));
        }
        s0 = warpSum(s0); s1 = warpSum(s1); s2 = warpSum(s2); s3 = warpSum(s3);
        float adh  = sel4(adv.x, adv.y, adv.z, adv.w, h);
        float invh = 1.f / (sel4(s0, s1, s2, s3, h) + 1e-16f);
        #pragma unroll 4
        for (int i = beg; i < end; i++) {
            int s = d_ssrc[i];
            float avh = sel4(d_als1[s * 4 + 0], d_als1[s * 4 + 1],
                             d_als1[s * 4 + 2], d_als1[s * 4 + 3], h);
            float wgt = expl(lrelu(avh + adh)) * invh;
            uint4 pv = *(const uint4*)(d_HWh + (size_t)s * 256 + lane * 8);
            float2 f0 = __half22float2(*(__half2*)&pv.x);
            float2 f1 = __half22float2(*(__half2*)&pv.y);
            float2 f2 = __half22float2(*(__half2*)&pv.z);
            float2 f3 = __half22float2(*(__half2*)&pv.w);
            acc[0] += f0.x * wgt; acc[1] += f0.y * wgt;
            acc[2] += f1.x * wgt; acc[3] += f1.y * wgt;
            acc[4] += f2.x * wgt; acc[5] += f2.y * wgt;
            acc[6] += f3.x * wgt; acc[7] += f3.y * wgt;
        }
    }
    const float* linrow = d_Y1lin + (size_t)w * 256 + lane * 8;
    float4 l0 = *(const float4*)(linrow);
    float4 l1 = *(const float4*)(linrow + 4);
    float4 g0 = *(const float4*)(g1bias + lane * 8);
    float4 g1v = *(const float4*)(g1bias + lane * 8 + 4);
    float4 o0, o1;
    o0.x = fmaxf(acc[0] + l0.x + g0.x, 0.f);
    o0.y = fmaxf(acc[1] + l0.y + g0.y, 0.f);
    o0.z = fmaxf(acc[2] + l0.z + g0.z, 0.f);
    o0.w = fmaxf(acc[3] + l0.w + g0.w, 0.f);
    o1.x = fmaxf(acc[4] + l1.x + g1v.x, 0.f);
    o1.y = fmaxf(acc[5] + l1.y + g1v.y, 0.f);
    o1.z = fmaxf(acc[6] + l1.z + g1v.z, 0.f);
    o1.w = fmaxf(acc[7] + l1.w + g1v.w, 0.f);
    float* orow = d_h1 + (size_t)w * HCC + lane * 8;
    *(float4*)(orow) = o0;
    *(float4*)(orow + 4) = o1;
}

__global__ void k_fold2(const float* __restrict__ g, const float* __restrict__ b,
                        const float* __restrict__ lin3W, const float* __restrict__ lin3b,
                        const float* __restrict__ g2W) {
    __shared__ float ssc[HCC], tsh[HCC];
    int tid = threadIdx.x;                    // 256
    float mu  = d_sum3[tid] * (1.f / NN);
    float var = d_sq3[tid] * (1.f / NN) - mu * mu;
    float sc  = rsqrtf(var + BN_EPS) * g[tid];
    ssc[tid] = sc;
    tsh[tid] = b[tid] - mu * sc;
    __syncthreads();
    #pragma unroll
    for (int j = 0; j < 4; j++) {
        float w = (j < 2) ? lin3W[tid * 2 + j] : g2W[tid * 2 + (j - 2)];
        d_W2effT[j * HCC + tid] = ssc[tid] * w;
    }
    if (tid < 4) {
        float acc = (tid < 2) ? lin3b[tid] : 0.f;
        for (int k = 0; k < HCC; k++) {
            float w = (tid < 2) ? lin3W[k * 2 + tid] : g2W[k * 2 + (tid - 2)];
            acc += tsh[k] * w;
        }
        d_c2[tid] = acc;
    }
}

__global__ void k_gemm2(const float* __restrict__ asrc, const float* __restrict__ adst) {
    __shared__ float Wsh[4 * HCC];
    int tid = threadIdx.x;
    for (int i = tid; i < 4 * HCC; i += blockDim.x) Wsh[i] = d_W2effT[i];
    __syncthreads();
    int w = (blockIdx.x * blockDim.x + tid) >> 5;
    int lane = tid & 31;
    if (w >= NN) return;
    const float* hrow = d_h1 + (size_t)w * HCC;
    float a0 = 0.f, a1 = 0.f, a2 = 0.f, a3 = 0.f;
    #pragma unroll
    for (int j = 0; j < 8; j++) {
        int k = lane + 32 * j;
        float hv = hrow[k];
        a0 += hv * Wsh[k];
        a1 += hv * Wsh[HCC + k];
        a2 += hv * Wsh[2 * HCC + k];
        a3 += hv * Wsh[3 * HCC + k];
    }
    a0 = warpSum(a0); a1 = warpSum(a1); a2 = warpSum(a2); a3 = warpSum(a3);
    if (lane == 0) {
        a0 += d_c2[0]; a1 += d_c2[1]; a2 += d_c2[2]; a3 += d_c2[3];
        d_Y2[w * 4 + 0] = a0;
        d_Y2[w * 4 + 1] = a1;
        d_Y2[w * 4 + 2] = a2;
        d_Y2[w * 4 + 3] = a3;
        d_als2[w] = a2 * asrc[0] + a3 * asrc[1];
        d_ald2[w] = a2 * adst[0] + a3 * adst[1];
    }
}

__global__ void k_edge2(const float* __restrict__ g2bias, float* __restrict__ out) {
    int w = (blockIdx.x * blockDim.x + threadIdx.x) >> 5;
    int lane = threadIdx.x & 31;
    if (w >= NN) return;
    int beg = d_rowptr[w], end = d_rowptr[w + 1];
    float a0 = 0.f, a1 = 0.f;
    if (end > beg) {
        float ad = d_ald2[w];
        float ssum = 0.f;
        #pragma unroll 2
        for (int i = beg + lane; i < end; i += 32) {
            ssum += expl(lrelu(d_als2[d_ssrc[i]] + ad));
        }
        float inv = 1.f / (warpSum(ssum) + 1e-16f);
        #pragma unroll 2
        for (int i = beg + lane; i < end; i += 32) {
            int sv = d_ssrc[i];
            float wgt = expl(lrelu(d_als2[sv] + ad)) * inv;
            a0 += d_Y2[sv * 4 + 2] * wgt;
            a1 += d_Y2[sv * 4 + 3] * wgt;
        }
        a0 = warpSum(a0);
        a1 = warpSum(a1);
    }
    if (lane == 0) {
        float v0 = d_Y2[w * 4 + 0] + g2bias[0] + a0;
        float v1 = d_Y2[w * 4 + 1] + g2bias[1] + a1;
        out[w * 2 + 0] = v0 > 0.f ? v0 : 0.f;
        out[w * 2 + 1] = v1 > 0.f ? v1 : 0.f;
    }
}

// ---------------- launch ----------------
// Side stream + events for graph fork/join. Created lazily on the FIRST call
// (the uncaptured correctness run) because stream/event creation is illegal
// during an active global capture. Work recorded per call is identical, so
// kernel_launch remains deterministic.
static cudaStream_t g_s1 = 0;
static cudaEvent_t  g_eFork = 0, g_eJoin = 0;

extern "C" void kernel_launch(void* const* d_in, const int* in_sizes, int n_in,
                              void* d_out, int out_size) {
    const float* x       = (const float*)d_in[0];
    const void*  ei      = (const void*)d_in[1];
    const float* bn1_g   = (const float*)d_in[2];
    const float* bn1_b   = (const float*)d_in[3];
    const float* bn3_g   = (const float*)d_in[4];
    const float* bn3_b   = (const float*)d_in[5];
    const float* lin1_W  = (const float*)d_in[6];
    const float* lin1_b  = (const float*)d_in[7];
    const float* lin3_W  = (const float*)d_in[8];
    const float* lin3_b  = (const float*)d_in[9];
    const float* g1_W    = (const float*)d_in[10];
    const float* g1_asrc = (const float*)d_in[11];
    const float* g1_adst = (const float*)d_in[12];
    const float* g1_bias = (const float*)d_in[13];
    const float* g2_W    = (const float*)d_in[14];
    const float* g2_asrc = (const float*)d_in[15];
    const float* g2_adst = (const float*)d_in[16];
    const float* g2_bias = (const float*)d_in[17];
    float* out = (float*)d_out;

    if (g_s1 == 0) {
        cudaStreamCreateWithFlags(&g_s1, cudaStreamNonBlocking);
        cudaEventCreateWithFlags(&g_eFork, cudaEventDisableTiming);
        cudaEventCreateWithFlags(&g_eJoin, cudaEventDisableTiming);
    }

    const int warpsGrid = (NN * 32 + 255) / 256;   // 6250 blocks (warp/node)

    // fork at t=0
    cudaEventRecord(g_eFork, 0);
    cudaStreamWaitEvent(g_s1, g_eFork, 0);

    // chain B (graph build) on side stream — overlaps with chain A
    k_zeroB<<<(NN + 255) / 256, 256, 0, g_s1>>>();
    k_detect<<<16, 256, 0, g_s1>>>((const long long*)ei);
    k_hist<<<784, 256, 0, g_s1>>>(ei);
    k_blocksum<<<NBLK, 256, 0, g_s1>>>();
    k_scanb<<<1, 64, 0, g_s1>>>();
    k_fill<<<NBLK, 1024, 0, g_s1>>>();
    k_scatter<<<784, 256, 0, g_s1>>>(ei);
    cudaEventRecord(g_eJoin, g_s1);

    // chain A (dense compute) on main stream
    k_zeroA<<<1, 256>>>();
    k_colstats_x<<<512, 256>>>(x);
    k_fold1<<<1, 512>>>(bn1_g, bn1_b, lin1_W, lin1_b, g1_W);
    dim3 g1grid(4, (NN + 127) / 128);
    k_gemm1<<<g1grid, 256>>>(x);
    k_alphas1<<<warpsGrid, 256>>>(g1_asrc, g1_adst);

    // join: edge1 needs CSR (chain B) + gemm1 outputs (chain A)
    cudaStreamWaitEvent(0, g_eJoin, 0);
    k_edge1<<<warpsGrid, 256>>>(g1_bias);
    k_colstats_h1<<<512, 256>>>();
    k_fold2<<<1, 256>>>(bn3_g, bn3_b, lin3_W, lin3_b, g2_W);
    k_gemm2<<<warpsGrid, 256>>>(g2_asrc, g2_adst);
    k_edge2<<<warpsGrid, 256>>>(g2_bias, out);
}

// round 14
// speedup vs baseline: 1.1136x; 1.1127x over previous
#include <cuda_runtime.h>
#include <cuda_fp16.h>
#include <cstdint>

#define NN 50000
#define FIN 128
#define HCC 256
#define EE 800000
#define BN_EPS 1e-5f

// ---------------- scratch (device globals; no allocation allowed) ----------------
__device__ __align__(16) __half d_Y1linh[(size_t)NN * 256];  // lin part in fp16
__device__ __align__(16) __half d_HWh[(size_t)NN * 256];     // hW in fp16
__device__ __align__(16) float  d_h1[(size_t)NN * HCC];
__device__ __align__(16) float  d_als1[NN * 4];
__device__ __align__(16) float  d_ald1[NN * 4];
__device__ __align__(16) float  d_Y2[NN * 4];
__device__ float d_als2[NN];
__device__ float d_ald2[NN];
__device__ int   d_deg[NN];
__device__ int   d_rowptr[NN + 1];
__device__ int   d_wpos[NN];
__device__ int   d_ssrc[EE];
__device__ float d_sum1[FIN], d_sq1[FIN];
__device__ float d_sum3[HCC], d_sq3[HCC];
__device__ __align__(16) float d_W1eff[FIN * 512];
__device__ float d_c1[512];
__device__ float d_W2effT[4 * HCC];
__device__ float d_c2[4];
__device__ int   d_is64;

// ---------------- helpers ----------------
__device__ __forceinline__ float warpSum(float v) {
    #pragma unroll
    for (int o = 16; o; o >>= 1) v += __shfl_xor_sync(0xffffffffu, v, o);
    return v;
}
__device__ __forceinline__ float lrelu(float x) { return x > 0.f ? x : 0.2f * x; }
__device__ __forceinline__ float sel4(float a, float b, float c, float d, int h) {
    return h < 2 ? (h == 0 ? a : b) : (h == 2 ? c : d);
}
__device__ __forceinline__ float expl(float e) { return __expf(fminf(e, 60.f)); }
__device__ __forceinline__ uint32_t f2tf(float x) {
    uint32_t r;
    asm("cvt.rna.tf32.f32 %0, %1;" : "=r"(r) : "f"(x));
    return r;
}
__device__ __forceinline__ void mma8(float* d, const uint32_t* a, const uint32_t* b) {
    asm volatile("mma.sync.aligned.m16n8k8.row.col.f32.tf32.tf32.f32 "
        "{%0,%1,%2,%3}, {%4,%5,%6,%7}, {%8,%9}, {%0,%1,%2,%3};"
        : "+f"(d[0]), "+f"(d[1]), "+f"(d[2]), "+f"(d[3])
        : "r"(a[0]), "r"(a[1]), "r"(a[2]), "r"(a[3]), "r"(b[0]), "r"(b[1]));
}

// ---------------- kernels ----------------
__global__ void k_zero() {
    int i = blockIdx.x * blockDim.x + threadIdx.x;
    if (i < NN) d_deg[i] = 0;
    if (i < FIN) { d_sum1[i] = 0.f; d_sq1[i] = 0.f; }
    if (i < HCC) { d_sum3[i] = 0.f; d_sq3[i] = 0.f; }
    if (i == 0) d_is64 = 1;
}

// sampling dtype probe: 4096 strided 8-byte words. int32-packed words look huge.
__global__ void k_detect(const long long* __restrict__ p) {
    int i = blockIdx.x * blockDim.x + threadIdx.x;     // 4096 threads
    long long v = p[(size_t)i * (EE / 4096)];
    if (v < 0 || v >= NN) d_is64 = 0;
}

__global__ void k_hist(const void* __restrict__ ei) {
    bool is64 = (d_is64 != 0);
    int stride = gridDim.x * blockDim.x;
    for (int e = blockIdx.x * blockDim.x + threadIdx.x; e < EE; e += stride) {
        int d = is64 ? (int)((const long long*)ei)[EE + e] : ((const int*)ei)[EE + e];
        if (d >= 0 && d < NN) atomicAdd(&d_deg[d], 1);
    }
}

// single-block scan: slow (~80us) but fully hidden on the side stream and
// occupies only ONE SM — leaves the chip to chain A (measured better than the
// multi-block decomposition, which contends with gemm1).
__global__ void k_scan() {                    // single block, 1024 threads
    __shared__ int tots[1024];
    int t = threadIdx.x;
    const int per = (NN + 1023) / 1024;
    int beg = t * per, end = min(beg + per, NN);
    int s = 0;
    for (int i = beg; i < end; i++) s += d_deg[i];
    tots[t] = s;
    __syncthreads();
    for (int off = 1; off < 1024; off <<= 1) {
        int v = (t >= off) ? tots[t - off] : 0;
        __syncthreads();
        tots[t] += v;
        __syncthreads();
    }
    int prefix = (t == 0) ? 0 : tots[t - 1];
    for (int i = beg; i < end; i++) {
        int dv = d_deg[i];
        d_rowptr[i] = prefix;
        d_wpos[i] = prefix;
        prefix += dv;
    }
    if (t == 1023) d_rowptr[NN] = prefix;
}

__global__ void k_scatter(const void* __restrict__ ei) {
    bool is64 = (d_is64 != 0);
    int stride = gridDim.x * blockDim.x;
    for (int e = blockIdx.x * blockDim.x + threadIdx.x; e < EE; e += stride) {
        int d, s;
        if (is64) {
            d = (int)((const long long*)ei)[EE + e];
            s = (int)((const long long*)ei)[e];
        } else {
            d = ((const int*)ei)[EE + e];
            s = ((const int*)ei)[e];
        }
        if (d >= 0 && d < NN) {
            int p = atomicAdd(&d_wpos[d], 1);
            d_ssrc[p] = (s >= 0 && s < NN) ? s : 0;
        }
    }
}

__global__ void k_colstats_x(const float* __restrict__ X) {
    __shared__ float s_s[FIN], s_q[FIN];
    int tid = threadIdx.x;                     // 256
    if (tid < FIN) { s_s[tid] = 0.f; s_q[tid] = 0.f; }
    __syncthreads();
    int lane = tid & 31;
    int nw = (gridDim.x * blockDim.x) >> 5;
    int gw = (blockIdx.x * blockDim.x + tid) >> 5;
    float s0 = 0, s1 = 0, s2 = 0, s3 = 0, q0 = 0, q1 = 0, q2 = 0, q3 = 0;
    #pragma unroll 4
    for (int r = gw; r < NN; r += nw) {
        float4 v = *(const float4*)(X + (size_t)r * FIN + lane * 4);
        s0 += v.x; q0 += v.x * v.x;
        s1 += v.y; q1 += v.y * v.y;
        s2 += v.z; q2 += v.z * v.z;
        s3 += v.w; q3 += v.w * v.w;
    }
    atomicAdd(&s_s[lane * 4 + 0], s0); atomicAdd(&s_q[lane * 4 + 0], q0);
    atomicAdd(&s_s[lane * 4 + 1], s1); atomicAdd(&s_q[lane * 4 + 1], q1);
    atomicAdd(&s_s[lane * 4 + 2], s2); atomicAdd(&s_q[lane * 4 + 2], q2);
    atomicAdd(&s_s[lane * 4 + 3], s3); atomicAdd(&s_q[lane * 4 + 3], q3);
    __syncthreads();
    if (tid < FIN) { atomicAdd(&d_sum1[tid], s_s[tid]); atomicAdd(&d_sq1[tid], s_q[tid]); }
}

__global__ void k_colstats_h1() {
    __shared__ float s_s[HCC], s_q[HCC];
    int tid = threadIdx.x;                     // 256
    s_s[tid] = 0.f; s_q[tid] = 0.f;
    __syncthreads();
    int lane = tid & 31;
    int nw = (gridDim.x * blockDim.x) >> 5;
    int gw = (blockIdx.x * blockDim.x + tid) >> 5;
    float s[8] = {0, 0, 0, 0, 0, 0, 0, 0}, q[8] = {0, 0, 0, 0, 0, 0, 0, 0};
    #pragma unroll 4
    for (int r = gw; r < NN; r += nw) {
        const float* row = d_h1 + (size_t)r * HCC;
        float4 v0 = *(const float4*)(row + lane * 4);
        float4 v1 = *(const float4*)(row + 128 + lane * 4);
        s[0] += v0.x; q[0] += v0.x * v0.x; s[1] += v0.y; q[1] += v0.y * v0.y;
        s[2] += v0.z; q[2] += v0.z * v0.z; s[3] += v0.w; q[3] += v0.w * v0.w;
        s[4] += v1.x; q[4] += v1.x * v1.x; s[5] += v1.y; q[5] += v1.y * v1.y;
        s[6] += v1.z; q[6] += v1.z * v1.z; s[7] += v1.w; q[7] += v1.w * v1.w;
    }
    #pragma unroll
    for (int i = 0; i < 4; i++) {
        atomicAdd(&s_s[lane * 4 + i], s[i]);       atomicAdd(&s_q[lane * 4 + i], q[i]);
        atomicAdd(&s_s[128 + lane * 4 + i], s[4 + i]); atomicAdd(&s_q[128 + lane * 4 + i], q[4 + i]);
    }
    __syncthreads();
    atomicAdd(&d_sum3[tid], s_s[tid]); atomicAdd(&d_sq3[tid], s_q[tid]);
}

// multi-block fold1: every block recomputes the 128 BN factors (cheap), then
// strides the 65K weight-scaling; block 0 also computes c1 (512 dots).
__global__ void k_fold1(const float* __restrict__ g, const float* __restrict__ b,
                        const float* __restrict__ lin1W, const float* __restrict__ lin1b,
                        const float* __restrict__ g1W) {
    __shared__ float ssc[FIN], tsh[FIN];
    int tid = threadIdx.x;                    // 512
    if (tid < FIN) {
        float mu  = d_sum1[tid] * (1.f / NN);
        float var = d_sq1[tid] * (1.f / NN) - mu * mu;
        float sc  = rsqrtf(var + BN_EPS) * g[tid];
        ssc[tid] = sc;
        tsh[tid] = b[tid] - mu * sc;
    }
    __syncthreads();
    if (blockIdx.x == 0) {
        int j = tid;
        float acc = (j < 256) ? lin1b[j] : 0.f;
        for (int k = 0; k < FIN; k++) {
            float w = (j < 256) ? lin1W[k * 256 + j] : g1W[k * 256 + (j - 256)];
            acc += tsh[k] * w;
        }
        d_c1[j] = acc;
    }
    int stride = gridDim.x * blockDim.x;
    for (int idx = blockIdx.x * blockDim.x + tid; idx < FIN * 512; idx += stride) {
        int k = idx >> 9, jj = idx & 511;
        float w = (jj < 256) ? lin1W[k * 256 + jj] : g1W[k * 256 + (jj - 256)];
        d_W1eff[idx] = ssc[k] * w;
    }
}

// Y1 = x @ W1eff + c1 via 3-term split-tf32 MMA (full fp32-class precision).
// Both outputs stored fp16: lin cols -> d_Y1linh ; HW cols -> d_HWh.
__global__ void __launch_bounds__(256) k_gemm1(const float* __restrict__ A) {
    __shared__ float As[128][36];
    __shared__ float Bs[32][128];
    int tid = threadIdx.x;
    int wid = tid >> 5, lane = tid & 31;
    int warpM = wid >> 2, warpN = wid & 3;
    int row0 = blockIdx.y * 128, col0 = blockIdx.x * 128;
    int rql = lane >> 2, kq = lane & 3;

    float acc[4][4][4];
    #pragma unroll
    for (int mi = 0; mi < 4; mi++)
        #pragma unroll
        for (int ni = 0; ni < 4; ni++)
            #pragma unroll
            for (int j = 0; j < 4; j++) acc[mi][ni][j] = 0.f;

    for (int kc = 0; kc < 4; kc++) {
        int kbase = kc * 32;
        #pragma unroll
        for (int i = 0; i < 4; i++) {
            int f = tid + i * 256;
            int r = f >> 3, q = (f & 7) * 4;
            int gr = row0 + r;
            float4 v = make_float4(0.f, 0.f, 0.f, 0.f);
            if (gr < NN) v = *(const float4*)(A + (size_t)gr * FIN + kbase + q);
            *(float4*)(&As[r][q]) = v;
        }
        #pragma unroll
        for (int i = 0; i < 4; i++) {
            int f = tid + i * 256;
            int kr = f >> 5, c = (f & 31) * 4;
            *(float4*)(&Bs[kr][c]) = *(const float4*)(d_W1eff + (size_t)(kbase + kr) * 512 + col0 + c);
        }
        __syncthreads();

        #pragma unroll
        for (int ks = 0; ks < 4; ks++) {
            int kb = ks * 8;
            uint32_t Ah[4][4], Al[4][4];
            #pragma unroll
            for (int mi = 0; mi < 4; mi++) {
                int r = warpM * 64 + mi * 16 + rql;
                float x0 = As[r][kb + kq];
                float x1 = As[r + 8][kb + kq];
                float x2 = As[r][kb + kq + 4];
                float x3 = As[r + 8][kb + kq + 4];
                Ah[mi][0] = f2tf(x0); Al[mi][0] = f2tf(x0 - __uint_as_float(Ah[mi][0]));
                Ah[mi][1] = f2tf(x1); Al[mi][1] = f2tf(x1 - __uint_as_float(Ah[mi][1]));
                Ah[mi][2] = f2tf(x2); Al[mi][2] = f2tf(x2 - __uint_as_float(Ah[mi][2]));
                Ah[mi][3] = f2tf(x3); Al[mi][3] = f2tf(x3 - __uint_as_float(Ah[mi][3]));
            }
            uint32_t Bh[4][2], Bl[4][2];
            #pragma unroll
            for (int ni = 0; ni < 4; ni++) {
                int c = warpN * 32 + ni * 8 + rql;
                float y0 = Bs[kb + kq][c];
                float y1 = Bs[kb + kq + 4][c];
                Bh[ni][0] = f2tf(y0); Bl[ni][0] = f2tf(y0 - __uint_as_float(Bh[ni][0]));
                Bh[ni][1] = f2tf(y1); Bl[ni][1] = f2tf(y1 - __uint_as_float(Bh[ni][1]));
            }
            #pragma unroll
            for (int mi = 0; mi < 4; mi++)
                #pragma unroll
                for (int ni = 0; ni < 4; ni++) {
                    mma8(acc[mi][ni], Al[mi], Bh[ni]);
                    mma8(acc[mi][ni], Ah[mi], Bl[ni]);
                    mma8(acc[mi][ni], Ah[mi], Bh[ni]);
                }
        }
        __syncthreads();
    }

    // epilogue: +c1, fp16 stores (both halves)
    bool isHW = (col0 >= 256);
    __half* dst = isHW ? d_HWh : d_Y1linh;
    int cbase = isHW ? (col0 - 256) : col0;
    int cq = (lane & 3) * 2;
    float2 bias[4];
    #pragma unroll
    for (int ni = 0; ni < 4; ni++) {
        int gc = col0 + warpN * 32 + ni * 8 + cq;
        bias[ni] = make_float2(d_c1[gc], d_c1[gc + 1]);
    }
    #pragma unroll
    for (int mi = 0; mi < 4; mi++) {
        int rr = row0 + warpM * 64 + mi * 16 + rql;
        #pragma unroll
        for (int ni = 0; ni < 4; ni++) {
            int cc = cbase + warpN * 32 + ni * 8 + cq;
            if (rr < NN)
                *(__half2*)(dst + (size_t)rr * 256 + cc) =
                    __floats2half2_rn(acc[mi][ni][0] + bias[ni].x, acc[mi][ni][1] + bias[ni].y);
            if (rr + 8 < NN)
                *(__half2*)(dst + (size_t)(rr + 8) * 256 + cc) =
                    __floats2half2_rn(acc[mi][ni][2] + bias[ni].x, acc[mi][ni][3] + bias[ni].y);
        }
    }
}

// attention logit projections from fp16 hW
__global__ void k_alphas1(const float* __restrict__ asrc, const float* __restrict__ adst) {
    int w = (blockIdx.x * blockDim.x + threadIdx.x) >> 5;
    int lane = threadIdx.x & 31;
    if (w >= NN) return;
    uint4 pv = *(const uint4*)(d_HWh + (size_t)w * 256 + lane * 8);
    float2 f0 = __half22float2(*(__half2*)&pv.x);
    float2 f1 = __half22float2(*(__half2*)&pv.y);
    float2 f2 = __half22float2(*(__half2*)&pv.z);
    float2 f3 = __half22float2(*(__half2*)&pv.w);
    float4 a0 = *(const float4*)(asrc + lane * 8);
    float4 a1 = *(const float4*)(asrc + lane * 8 + 4);
    float4 b0 = *(const float4*)(adst + lane * 8);
    float4 b1 = *(const float4*)(adst + lane * 8 + 4);
    float s = f0.x * a0.x + f0.y * a0.y + f1.x * a0.z + f1.y * a0.w
            + f2.x * a1.x + f2.y * a1.y + f3.x * a1.z + f3.y * a1.w;
    float d = f0.x * b0.x + f0.y * b0.y + f1.x * b0.z + f1.y * b0.w
            + f2.x * b1.x + f2.y * b1.y + f3.x * b1.z + f3.y * b1.w;
    #pragma unroll
    for (int o = 1; o < 8; o <<= 1) {
        s += __shfl_xor_sync(0xffffffffu, s, o);
        d += __shfl_xor_sync(0xffffffffu, d, o);
    }
    if ((lane & 7) == 0) {
        d_als1[w * 4 + (lane >> 3)] = s;
        d_ald1[w * 4 + (lane >> 3)] = d;
    }
}

// layer-1 edge aggregation (max-free softmax) + combine + relu -> h1. One warp per dst node.
__global__ void k_edge1(const float* __restrict__ g1bias) {
    int w = (blockIdx.x * blockDim.x + threadIdx.x) >> 5;
    int lane = threadIdx.x & 31;
    if (w >= NN) return;
    int beg = d_rowptr[w], end = d_rowptr[w + 1];
    int h = lane >> 3;
    float acc[8];
    #pragma unroll
    for (int j = 0; j < 8; j++) acc[j] = 0.f;

    if (end > beg) {
        float4 adv = *(const float4*)(d_ald1 + w * 4);
        float s0 = 0.f, s1 = 0.f, s2 = 0.f, s3 = 0.f;
        #pragma unroll 2
        for (int i = beg + lane; i < end; i += 32) {
            int s = d_ssrc[i];
            float4 avv = *(const float4*)(d_als1 + s * 4);
            s0 += expl(lrelu(avv.x + adv.x));
            s1 += expl(lrelu(avv.y + adv.y));
            s2 += expl(lrelu(avv.z + adv.z));
            s3 += expl(lrelu(avv.w + adv.w));
        }
        s0 = warpSum(s0); s1 = warpSum(s1); s2 = warpSum(s2); s3 = warpSum(s3);
        float adh  = sel4(adv.x, adv.y, adv.z, adv.w, h);
        float invh = 1.f / (sel4(s0, s1, s2, s3, h) + 1e-16f);
        #pragma unroll 4
        for (int i = beg; i < end; i++) {
            int s = d_ssrc[i];
            float avh = sel4(d_als1[s * 4 + 0], d_als1[s * 4 + 1],
                             d_als1[s * 4 + 2], d_als1[s * 4 + 3], h);
            float wgt = expl(lrelu(avh + adh)) * invh;
            uint4 pv = *(const uint4*)(d_HWh + (size_t)s * 256 + lane * 8);
            float2 f0 = __half22float2(*(__half2*)&pv.x);
            float2 f1 = __half22float2(*(__half2*)&pv.y);
            float2 f2 = __half22float2(*(__half2*)&pv.z);
            float2 f3 = __half22float2(*(__half2*)&pv.w);
            acc[0] += f0.x * wgt; acc[1] += f0.y * wgt;
            acc[2] += f1.x * wgt; acc[3] += f1.y * wgt;
            acc[4] += f2.x * wgt; acc[5] += f2.y * wgt;
            acc[6] += f3.x * wgt; acc[7] += f3.y * wgt;
        }
    }
    uint4 lv = *(const uint4*)(d_Y1linh + (size_t)w * 256 + lane * 8);
    float2 l0 = __half22float2(*(__half2*)&lv.x);
    float2 l1 = __half22float2(*(__half2*)&lv.y);
    float2 l2 = __half22float2(*(__half2*)&lv.z);
    float2 l3 = __half22float2(*(__half2*)&lv.w);
    float4 g0 = *(const float4*)(g1bias + lane * 8);
    float4 g1v = *(const float4*)(g1bias + lane * 8 + 4);
    float4 o0, o1;
    o0.x = fmaxf(acc[0] + l0.x + g0.x, 0.f);
    o0.y = fmaxf(acc[1] + l0.y + g0.y, 0.f);
    o0.z = fmaxf(acc[2] + l1.x + g0.z, 0.f);
    o0.w = fmaxf(acc[3] + l1.y + g0.w, 0.f);
    o1.x = fmaxf(acc[4] + l2.x + g1v.x, 0.f);
    o1.y = fmaxf(acc[5] + l2.y + g1v.y, 0.f);
    o1.z = fmaxf(acc[6] + l3.x + g1v.z, 0.f);
    o1.w = fmaxf(acc[7] + l3.y + g1v.w, 0.f);
    float* orow = d_h1 + (size_t)w * HCC + lane * 8;
    *(float4*)(orow) = o0;
    *(float4*)(orow + 4) = o1;
}

__global__ void k_fold2(const float* __restrict__ g, const float* __restrict__ b,
                        const float* __restrict__ lin3W, const float* __restrict__ lin3b,
                        const float* __restrict__ g2W) {
    __shared__ float ssc[HCC], tsh[HCC];
    int tid = threadIdx.x;                    // 256
    float mu  = d_sum3[tid] * (1.f / NN);
    float var = d_sq3[tid] * (1.f / NN) - mu * mu;
    float sc  = rsqrtf(var + BN_EPS) * g[tid];
    ssc[tid] = sc;
    tsh[tid] = b[tid] - mu * sc;
    __syncthreads();
    #pragma unroll
    for (int j = 0; j < 4; j++) {
        float w = (j < 2) ? lin3W[tid * 2 + j] : g2W[tid * 2 + (j - 2)];
        d_W2effT[j * HCC + tid] = ssc[tid] * w;
    }
    if (tid < 4) {
        float acc = (tid < 2) ? lin3b[tid] : 0.f;
        for (int k = 0; k < HCC; k++) {
            float w = (tid < 2) ? lin3W[k * 2 + tid] : g2W[k * 2 + (tid - 2)];
            acc += tsh[k] * w;
        }
        d_c2[tid] = acc;
    }
}

__global__ void k_gemm2(const float* __restrict__ asrc, const float* __restrict__ adst) {
    __shared__ float Wsh[4 * HCC];
    int tid = threadIdx.x;
    for (int i = tid; i < 4 * HCC; i += blockDim.x) Wsh[i] = d_W2effT[i];
    __syncthreads();
    int w = (blockIdx.x * blockDim.x + tid) >> 5;
    int lane = tid & 31;
    if (w >= NN) return;
    const float* hrow = d_h1 + (size_t)w * HCC;
    float a0 = 0.f, a1 = 0.f, a2 = 0.f, a3 = 0.f;
    #pragma unroll
    for (int j = 0; j < 8; j++) {
        int k = lane + 32 * j;
        float hv = hrow[k];
        a0 += hv * Wsh[k];
        a1 += hv * Wsh[HCC + k];
        a2 += hv * Wsh[2 * HCC + k];
        a3 += hv * Wsh[3 * HCC + k];
    }
    a0 = warpSum(a0); a1 = warpSum(a1); a2 = warpSum(a2); a3 = warpSum(a3);
    if (lane == 0) {
        a0 += d_c2[0]; a1 += d_c2[1]; a2 += d_c2[2]; a3 += d_c2[3];
        d_Y2[w * 4 + 0] = a0;
        d_Y2[w * 4 + 1] = a1;
        d_Y2[w * 4 + 2] = a2;
        d_Y2[w * 4 + 3] = a3;
        d_als2[w] = a2 * asrc[0] + a3 * asrc[1];
        d_ald2[w] = a2 * adst[0] + a3 * adst[1];
    }
}

__global__ void k_edge2(const float* __restrict__ g2bias, float* __restrict__ out) {
    int w = (blockIdx.x * blockDim.x + threadIdx.x) >> 5;
    int lane = threadIdx.x & 31;
    if (w >= NN) return;
    int beg = d_rowptr[w], end = d_rowptr[w + 1];
    float a0 = 0.f, a1 = 0.f;
    if (end > beg) {
        float ad = d_ald2[w];
        float ssum = 0.f;
        #pragma unroll 2
        for (int i = beg + lane; i < end; i += 32) {
            ssum += expl(lrelu(d_als2[d_ssrc[i]] + ad));
        }
        float inv = 1.f / (warpSum(ssum) + 1e-16f);
        #pragma unroll 2
        for (int i = beg + lane; i < end; i += 32) {
            int sv = d_ssrc[i];
            float wgt = expl(lrelu(d_als2[sv] + ad)) * inv;
            a0 += d_Y2[sv * 4 + 2] * wgt;
            a1 += d_Y2[sv * 4 + 3] * wgt;
        }
        a0 = warpSum(a0);
        a1 = warpSum(a1);
    }
    if (lane == 0) {
        float v0 = d_Y2[w * 4 + 0] + g2bias[0] + a0;
        float v1 = d_Y2[w * 4 + 1] + g2bias[1] + a1;
        out[w * 2 + 0] = v0 > 0.f ? v0 : 0.f;
        out[w * 2 + 1] = v1 > 0.f ? v1 : 0.f;
    }
}

// ---------------- launch ----------------
// Side stream + events for graph fork/join. Created lazily on the FIRST call
// (the uncaptured correctness run) because stream/event creation is illegal
// during an active global capture. Work recorded per call is identical, so
// kernel_launch remains deterministic.
static cudaStream_t g_s1 = 0;
static cudaEvent_t  g_eFork = 0, g_eJoin = 0;

extern "C" void kernel_launch(void* const* d_in, const int* in_sizes, int n_in,
                              void* d_out, int out_size) {
    const float* x       = (const float*)d_in[0];
    const void*  ei      = (const void*)d_in[1];
    const float* bn1_g   = (const float*)d_in[2];
    const float* bn1_b   = (const float*)d_in[3];
    const float* bn3_g   = (const float*)d_in[4];
    const float* bn3_b   = (const float*)d_in[5];
    const float* lin1_W  = (const float*)d_in[6];
    const float* lin1_b  = (const float*)d_in[7];
    const float* lin3_W  = (const float*)d_in[8];
    const float* lin3_b  = (const float*)d_in[9];
    const float* g1_W    = (const float*)d_in[10];
    const float* g1_asrc = (const float*)d_in[11];
    const float* g1_adst = (const float*)d_in[12];
    const float* g1_bias = (const float*)d_in[13];
    const float* g2_W    = (const float*)d_in[14];
    const float* g2_asrc = (const float*)d_in[15];
    const float* g2_adst = (const float*)d_in[16];
    const float* g2_bias = (const float*)d_in[17];
    float* out = (float*)d_out;

    if (g_s1 == 0) {
        cudaStreamCreateWithFlags(&g_s1, cudaStreamNonBlocking);
        cudaEventCreateWithFlags(&g_eFork, cudaEventDisableTiming);
        cudaEventCreateWithFlags(&g_eJoin, cudaEventDisableTiming);
    }

    const int warpsGrid = (NN * 32 + 255) / 256;   // 6250 blocks (warp/node)

    // common init on main stream
    k_zero<<<(NN + 255) / 256, 256>>>();
    cudaEventRecord(g_eFork, 0);
    cudaStreamWaitEvent(g_s1, g_eFork, 0);

    // chain B (graph build) on side stream — overlaps with chain A
    k_detect<<<16, 256, 0, g_s1>>>((const long long*)ei);
    k_hist<<<784, 256, 0, g_s1>>>(ei);
    k_scan<<<1, 1024, 0, g_s1>>>();
    k_scatter<<<784, 256, 0, g_s1>>>(ei);
    cudaEventRecord(g_eJoin, g_s1);

    // chain A (dense compute) on main stream
    k_colstats_x<<<512, 256>>>(x);
    k_fold1<<<16, 512>>>(bn1_g, bn1_b, lin1_W, lin1_b, g1_W);
    dim3 g1grid(4, (NN + 127) / 128);
    k_gemm1<<<g1grid, 256>>>(x);
    k_alphas1<<<warpsGrid, 256>>>(g1_asrc, g1_adst);

    // join: edge1 needs CSR (chain B) + gemm1 outputs (chain A)
    cudaStreamWaitEvent(0, g_eJoin, 0);
    k_edge1<<<warpsGrid, 256>>>(g1_bias);
    k_colstats_h1<<<512, 256>>>();
    k_fold2<<<1, 256>>>(bn3_g, bn3_b, lin3_W, lin3_b, g2_W);
    k_gemm2<<<warpsGrid, 256>>>(g2_asrc, g2_adst);
    k_edge2<<<warpsGrid, 256>>>(g2_bias, out);
}

// round 16
// speedup vs baseline: 1.1216x; 1.0072x over previous
#include <cuda_runtime.h>
#include <cuda_fp16.h>
#include <cstdint>

#define NN 50000
#define FIN 128
#define HCC 256
#define EE 800000
#define BN_EPS 1e-5f

// ---------------- scratch (device globals; no allocation allowed) ----------------
__device__ __align__(16) __half d_Y1linh[(size_t)NN * 256];  // lin part, fp16
__device__ __align__(16) __half d_HWh[(size_t)NN * 256];     // hW, fp16
__device__ __align__(16) __half d_h1h[(size_t)NN * HCC];     // layer-1 output, fp16
__device__ __align__(16) float  d_als1[NN * 4];
__device__ __align__(16) float  d_ald1[NN * 4];
__device__ __align__(16) float  d_Y2[NN * 4];
__device__ float d_als2[NN];
__device__ float d_ald2[NN];
__device__ int   d_deg[NN];
__device__ int   d_rowptr[NN + 1];
__device__ int   d_wpos[NN];
__device__ int   d_ssrc[EE];
__device__ float d_sum1[FIN], d_sq1[FIN];
__device__ float d_sum3[HCC], d_sq3[HCC];
__device__ __align__(16) float d_W1eff[FIN * 512];
__device__ float d_c1[512];
__device__ float d_W2effT[4 * HCC];
__device__ float d_c2[4];
__device__ int   d_is64;

// ---------------- helpers ----------------
__device__ __forceinline__ float warpSum(float v) {
    #pragma unroll
    for (int o = 16; o; o >>= 1) v += __shfl_xor_sync(0xffffffffu, v, o);
    return v;
}
__device__ __forceinline__ float lrelu(float x) { return x > 0.f ? x : 0.2f * x; }
__device__ __forceinline__ float sel4(float a, float b, float c, float d, int h) {
    return h < 2 ? (h == 0 ? a : b) : (h == 2 ? c : d);
}
__device__ __forceinline__ float expl(float e) { return __expf(fminf(e, 60.f)); }
__device__ __forceinline__ uint32_t f2tf(float x) {
    uint32_t r;
    asm("cvt.rna.tf32.f32 %0, %1;" : "=r"(r) : "f"(x));
    return r;
}
__device__ __forceinline__ void mma8(float* d, const uint32_t* a, const uint32_t* b) {
    asm volatile("mma.sync.aligned.m16n8k8.row.col.f32.tf32.tf32.f32 "
        "{%0,%1,%2,%3}, {%4,%5,%6,%7}, {%8,%9}, {%0,%1,%2,%3};"
        : "+f"(d[0]), "+f"(d[1]), "+f"(d[2]), "+f"(d[3])
        : "r"(a[0]), "r"(a[1]), "r"(a[2]), "r"(a[3]), "r"(b[0]), "r"(b[1]));
}

// ---------------- kernels ----------------
__global__ void k_zero() {
    int i = blockIdx.x * blockDim.x + threadIdx.x;
    if (i < NN) d_deg[i] = 0;
    if (i < FIN) { d_sum1[i] = 0.f; d_sq1[i] = 0.f; }
    if (i < HCC) { d_sum3[i] = 0.f; d_sq3[i] = 0.f; }
    if (i == 0) d_is64 = 1;
}

// sampling dtype probe: 4096 strided 8-byte words. int32-packed words look huge.
__global__ void k_detect(const long long* __restrict__ p) {
    int i = blockIdx.x * blockDim.x + threadIdx.x;     // 4096 threads
    long long v = p[(size_t)i * (EE / 4096)];
    if (v < 0 || v >= NN) d_is64 = 0;
}

__global__ void k_hist(const void* __restrict__ ei) {
    bool is64 = (d_is64 != 0);
    int stride = gridDim.x * blockDim.x;
    for (int e = blockIdx.x * blockDim.x + threadIdx.x; e < EE; e += stride) {
        int d = is64 ? (int)((const long long*)ei)[EE + e] : ((const int*)ei)[EE + e];
        if (d >= 0 && d < NN) atomicAdd(&d_deg[d], 1);
    }
}

// single-block scan: slow (~80us) but fully hidden on the side stream and
// occupies only ONE SM — leaves the chip to chain A.
__global__ void k_scan() {                    // single block, 1024 threads
    __shared__ int tots[1024];
    int t = threadIdx.x;
    const int per = (NN + 1023) / 1024;
    int beg = t * per, end = min(beg + per, NN);
    int s = 0;
    for (int i = beg; i < end; i++) s += d_deg[i];
    tots[t] = s;
    __syncthreads();
    for (int off = 1; off < 1024; off <<= 1) {
        int v = (t >= off) ? tots[t - off] : 0;
        __syncthreads();
        tots[t] += v;
        __syncthreads();
    }
    int prefix = (t == 0) ? 0 : tots[t - 1];
    for (int i = beg; i < end; i++) {
        int dv = d_deg[i];
        d_rowptr[i] = prefix;
        d_wpos[i] = prefix;
        prefix += dv;
    }
    if (t == 1023) d_rowptr[NN] = prefix;
}

__global__ void k_scatter(const void* __restrict__ ei) {
    bool is64 = (d_is64 != 0);
    int stride = gridDim.x * blockDim.x;
    for (int e = blockIdx.x * blockDim.x + threadIdx.x; e < EE; e += stride) {
        int d, s;
        if (is64) {
            d = (int)((const long long*)ei)[EE + e];
            s = (int)((const long long*)ei)[e];
        } else {
            d = ((const int*)ei)[EE + e];
            s = ((const int*)ei)[e];
        }
        if (d >= 0 && d < NN) {
            int p = atomicAdd(&d_wpos[d], 1);
            d_ssrc[p] = (s >= 0 && s < NN) ? s : 0;
        }
    }
}

__global__ void k_colstats_x(const float* __restrict__ X) {
    __shared__ float s_s[FIN], s_q[FIN];
    int tid = threadIdx.x;                     // 256
    if (tid < FIN) { s_s[tid] = 0.f; s_q[tid] = 0.f; }
    __syncthreads();
    int lane = tid & 31;
    int nw = (gridDim.x * blockDim.x) >> 5;
    int gw = (blockIdx.x * blockDim.x + tid) >> 5;
    float s0 = 0, s1 = 0, s2 = 0, s3 = 0, q0 = 0, q1 = 0, q2 = 0, q3 = 0;
    #pragma unroll 4
    for (int r = gw; r < NN; r += nw) {
        float4 v = *(const float4*)(X + (size_t)r * FIN + lane * 4);
        s0 += v.x; q0 += v.x * v.x;
        s1 += v.y; q1 += v.y * v.y;
        s2 += v.z; q2 += v.z * v.z;
        s3 += v.w; q3 += v.w * v.w;
    }
    atomicAdd(&s_s[lane * 4 + 0], s0); atomicAdd(&s_q[lane * 4 + 0], q0);
    atomicAdd(&s_s[lane * 4 + 1], s1); atomicAdd(&s_q[lane * 4 + 1], q1);
    atomicAdd(&s_s[lane * 4 + 2], s2); atomicAdd(&s_q[lane * 4 + 2], q2);
    atomicAdd(&s_s[lane * 4 + 3], s3); atomicAdd(&s_q[lane * 4 + 3], q3);
    __syncthreads();
    if (tid < FIN) { atomicAdd(&d_sum1[tid], s_s[tid]); atomicAdd(&d_sq1[tid], s_q[tid]); }
}

// h1 column stats from fp16 (lane covers 8 contiguous cols)
__global__ void k_colstats_h1() {
    __shared__ float s_s[HCC], s_q[HCC];
    int tid = threadIdx.x;                     // 256
    s_s[tid] = 0.f; s_q[tid] = 0.f;
    __syncthreads();
    int lane = tid & 31;
    int nw = (gridDim.x * blockDim.x) >> 5;
    int gw = (blockIdx.x * blockDim.x + tid) >> 5;
    float s[8] = {0, 0, 0, 0, 0, 0, 0, 0}, q[8] = {0, 0, 0, 0, 0, 0, 0, 0};
    #pragma unroll 4
    for (int r = gw; r < NN; r += nw) {
        uint4 pv = *(const uint4*)(d_h1h + (size_t)r * HCC + lane * 8);
        float2 f0 = __half22float2(*(__half2*)&pv.x);
        float2 f1 = __half22float2(*(__half2*)&pv.y);
        float2 f2 = __half22float2(*(__half2*)&pv.z);
        float2 f3 = __half22float2(*(__half2*)&pv.w);
        s[0] += f0.x; q[0] += f0.x * f0.x; s[1] += f0.y; q[1] += f0.y * f0.y;
        s[2] += f1.x; q[2] += f1.x * f1.x; s[3] += f1.y; q[3] += f1.y * f1.y;
        s[4] += f2.x; q[4] += f2.x * f2.x; s[5] += f2.y; q[5] += f2.y * f2.y;
        s[6] += f3.x; q[6] += f3.x * f3.x; s[7] += f3.y; q[7] += f3.y * f3.y;
    }
    #pragma unroll
    for (int i = 0; i < 8; i++) {
        atomicAdd(&s_s[lane * 8 + i], s[i]);
        atomicAdd(&s_q[lane * 8 + i], q[i]);
    }
    __syncthreads();
    atomicAdd(&d_sum3[tid], s_s[tid]); atomicAdd(&d_sq3[tid], s_q[tid]);
}

// multi-block fold1
__global__ void k_fold1(const float* __restrict__ g, const float* __restrict__ b,
                        const float* __restrict__ lin1W, const float* __restrict__ lin1b,
                        const float* __restrict__ g1W) {
    __shared__ float ssc[FIN], tsh[FIN];
    int tid = threadIdx.x;                    // 512
    if (tid < FIN) {
        float mu  = d_sum1[tid] * (1.f / NN);
        float var = d_sq1[tid] * (1.f / NN) - mu * mu;
        float sc  = rsqrtf(var + BN_EPS) * g[tid];
        ssc[tid] = sc;
        tsh[tid] = b[tid] - mu * sc;
    }
    __syncthreads();
    if (blockIdx.x == 0) {
        int j = tid;
        float acc = (j < 256) ? lin1b[j] : 0.f;
        for (int k = 0; k < FIN; k++) {
            float w = (j < 256) ? lin1W[k * 256 + j] : g1W[k * 256 + (j - 256)];
            acc += tsh[k] * w;
        }
        d_c1[j] = acc;
    }
    int stride = gridDim.x * blockDim.x;
    for (int idx = blockIdx.x * blockDim.x + tid; idx < FIN * 512; idx += stride) {
        int k = idx >> 9, jj = idx & 511;
        float w = (jj < 256) ? lin1W[k * 256 + jj] : g1W[k * 256 + (jj - 256)];
        d_W1eff[idx] = ssc[k] * w;
    }
}

// Y1 = x @ W1eff + c1 via 3-term split-tf32 MMA; fp16 outputs.
__global__ void __launch_bounds__(256) k_gemm1(const float* __restrict__ A) {
    __shared__ float As[128][36];
    __shared__ float Bs[32][128];
    int tid = threadIdx.x;
    int wid = tid >> 5, lane = tid & 31;
    int warpM = wid >> 2, warpN = wid & 3;
    int row0 = blockIdx.y * 128, col0 = blockIdx.x * 128;
    int rql = lane >> 2, kq = lane & 3;

    float acc[4][4][4];
    #pragma unroll
    for (int mi = 0; mi < 4; mi++)
        #pragma unroll
        for (int ni = 0; ni < 4; ni++)
            #pragma unroll
            for (int j = 0; j < 4; j++) acc[mi][ni][j] = 0.f;

    for (int kc = 0; kc < 4; kc++) {
        int kbase = kc * 32;
        #pragma unroll
        for (int i = 0; i < 4; i++) {
            int f = tid + i * 256;
            int r = f >> 3, q = (f & 7) * 4;
            int gr = row0 + r;
            float4 v = make_float4(0.f, 0.f, 0.f, 0.f);
            if (gr < NN) v = *(const float4*)(A + (size_t)gr * FIN + kbase + q);
            *(float4*)(&As[r][q]) = v;
        }
        #pragma unroll
        for (int i = 0; i < 4; i++) {
            int f = tid + i * 256;
            int kr = f >> 5, c = (f & 31) * 4;
            *(float4*)(&Bs[kr][c]) = *(const float4*)(d_W1eff + (size_t)(kbase + kr) * 512 + col0 + c);
        }
        __syncthreads();

        #pragma unroll
        for (int ks = 0; ks < 4; ks++) {
            int kb = ks * 8;
            uint32_t Ah[4][4], Al[4][4];
            #pragma unroll
            for (int mi = 0; mi < 4; mi++) {
                int r = warpM * 64 + mi * 16 + rql;
                float x0 = As[r][kb + kq];
                float x1 = As[r + 8][kb + kq];
                float x2 = As[r][kb + kq + 4];
                float x3 = As[r + 8][kb + kq + 4];
                Ah[mi][0] = f2tf(x0); Al[mi][0] = f2tf(x0 - __uint_as_float(Ah[mi][0]));
                Ah[mi][1] = f2tf(x1); Al[mi][1] = f2tf(x1 - __uint_as_float(Ah[mi][1]));
                Ah[mi][2] = f2tf(x2); Al[mi][2] = f2tf(x2 - __uint_as_float(Ah[mi][2]));
                Ah[mi][3] = f2tf(x3); Al[mi][3] = f2tf(x3 - __uint_as_float(Ah[mi][3]));
            }
            uint32_t Bh[4][2], Bl[4][2];
            #pragma unroll
            for (int ni = 0; ni < 4; ni++) {
                int c = warpN * 32 + ni * 8 + rql;
                float y0 = Bs[kb + kq][c];
                float y1 = Bs[kb + kq + 4][c];
                Bh[ni][0] = f2tf(y0); Bl[ni][0] = f2tf(y0 - __uint_as_float(Bh[ni][0]));
                Bh[ni][1] = f2tf(y1); Bl[ni][1] = f2tf(y1 - __uint_as_float(Bh[ni][1]));
            }
            #pragma unroll
            for (int mi = 0; mi < 4; mi++)
                #pragma unroll
                for (int ni = 0; ni < 4; ni++) {
                    mma8(acc[mi][ni], Al[mi], Bh[ni]);
                    mma8(acc[mi][ni], Ah[mi], Bl[ni]);
                    mma8(acc[mi][ni], Ah[mi], Bh[ni]);
                }
        }
        __syncthreads();
    }

    // epilogue: +c1, fp16 stores
    bool isHW = (col0 >= 256);
    __half* dst = isHW ? d_HWh : d_Y1linh;
    int cbase = isHW ? (col0 - 256) : col0;
    int cq = (lane & 3) * 2;
    float2 bias[4];
    #pragma unroll
    for (int ni = 0; ni < 4; ni++) {
        int gc = col0 + warpN * 32 + ni * 8 + cq;
        bias[ni] = make_float2(d_c1[gc], d_c1[gc + 1]);
    }
    #pragma unroll
    for (int mi = 0; mi < 4; mi++) {
        int rr = row0 + warpM * 64 + mi * 16 + rql;
        #pragma unroll
        for (int ni = 0; ni < 4; ni++) {
            int cc = cbase + warpN * 32 + ni * 8 + cq;
            if (rr < NN)
                *(__half2*)(dst + (size_t)rr * 256 + cc) =
                    __floats2half2_rn(acc[mi][ni][0] + bias[ni].x, acc[mi][ni][1] + bias[ni].y);
            if (rr + 8 < NN)
                *(__half2*)(dst + (size_t)(rr + 8) * 256 + cc) =
                    __floats2half2_rn(acc[mi][ni][2] + bias[ni].x, acc[mi][ni][3] + bias[ni].y);
        }
    }
}

// attention logit projections from fp16 hW
__global__ void k_alphas1(const float* __restrict__ asrc, const float* __restrict__ adst) {
    int w = (blockIdx.x * blockDim.x + threadIdx.x) >> 5;
    int lane = threadIdx.x & 31;
    if (w >= NN) return;
    uint4 pv = *(const uint4*)(d_HWh + (size_t)w * 256 + lane * 8);
    float2 f0 = __half22float2(*(__half2*)&pv.x);
    float2 f1 = __half22float2(*(__half2*)&pv.y);
    float2 f2 = __half22float2(*(__half2*)&pv.z);
    float2 f3 = __half22float2(*(__half2*)&pv.w);
    float4 a0 = *(const float4*)(asrc + lane * 8);
    float4 a1 = *(const float4*)(asrc + lane * 8 + 4);
    float4 b0 = *(const float4*)(adst + lane * 8);
    float4 b1 = *(const float4*)(adst + lane * 8 + 4);
    float s = f0.x * a0.x + f0.y * a0.y + f1.x * a0.z + f1.y * a0.w
            + f2.x * a1.x + f2.y * a1.y + f3.x * a1.z + f3.y * a1.w;
    float d = f0.x * b0.x + f0.y * b0.y + f1.x * b0.z + f1.y * b0.w
            + f2.x * b1.x + f2.y * b1.y + f3.x * b1.z + f3.y * b1.w;
    #pragma unroll
    for (int o = 1; o < 8; o <<= 1) {
        s += __shfl_xor_sync(0xffffffffu, s, o);
        d += __shfl_xor_sync(0xffffffffu, d, o);
    }
    if ((lane & 7) == 0) {
        d_als1[w * 4 + (lane >> 3)] = s;
        d_ald1[w * 4 + (lane >> 3)] = d;
    }
}

// layer-1 edge aggregation (max-free softmax) + combine + relu -> h1 (fp16).
__global__ void k_edge1(const float* __restrict__ g1bias) {
    int w = (blockIdx.x * blockDim.x + threadIdx.x) >> 5;
    int lane = threadIdx.x & 31;
    if (w >= NN) return;
    int beg = d_rowptr[w], end = d_rowptr[w + 1];
    int h = lane >> 3;
    float acc[8];
    #pragma unroll
    for (int j = 0; j < 8; j++) acc[j] = 0.f;

    if (end > beg) {
        float4 adv = *(const float4*)(d_ald1 + w * 4);
        float s0 = 0.f, s1 = 0.f, s2 = 0.f, s3 = 0.f;
        #pragma unroll 2
        for (int i = beg + lane; i < end; i += 32) {
            int s = d_ssrc[i];
            float4 avv = *(const float4*)(d_als1 + s * 4);
            s0 += expl(lrelu(avv.x + adv.x));
            s1 += expl(lrelu(avv.y + adv.y));
            s2 += expl(lrelu(avv.z + adv.z));
            s3 += expl(lrelu(avv.w + adv.w));
        }
        s0 = warpSum(s0); s1 = warpSum(s1); s2 = warpSum(s2); s3 = warpSum(s3);
        float adh  = sel4(adv.x, adv.y, adv.z, adv.w, h);
        float invh = 1.f / (sel4(s0, s1, s2, s3, h) + 1e-16f);
        #pragma unroll 4
        for (int i = beg; i < end; i++) {
            int s = d_ssrc[i];
            float avh = sel4(d_als1[s * 4 + 0], d_als1[s * 4 + 1],
                             d_als1[s * 4 + 2], d_als1[s * 4 + 3], h);
            float wgt = expl(lrelu(avh + adh)) * invh;
            uint4 pv = *(const uint4*)(d_HWh + (size_t)s * 256 + lane * 8);
            float2 f0 = __half22float2(*(__half2*)&pv.x);
            float2 f1 = __half22float2(*(__half2*)&pv.y);
            float2 f2 = __half22float2(*(__half2*)&pv.z);
            float2 f3 = __half22float2(*(__half2*)&pv.w);
            acc[0] += f0.x * wgt; acc[1] += f0.y * wgt;
            acc[2] += f1.x * wgt; acc[3] += f1.y * wgt;
            acc[4] += f2.x * wgt; acc[5] += f2.y * wgt;
            acc[6] += f3.x * wgt; acc[7] += f3.y * wgt;
        }
    }
    uint4 lv = *(const uint4*)(d_Y1linh + (size_t)w * 256 + lane * 8);
    float2 l0 = __half22float2(*(__half2*)&lv.x);
    float2 l1 = __half22float2(*(__half2*)&lv.y);
    float2 l2 = __half22float2(*(__half2*)&lv.z);
    float2 l3 = __half22float2(*(__half2*)&lv.w);
    float4 g0 = *(const float4*)(g1bias + lane * 8);
    float4 g1v = *(const float4*)(g1bias + lane * 8 + 4);
    float o[8];
    o[0] = fmaxf(acc[0] + l0.x + g0.x, 0.f);
    o[1] = fmaxf(acc[1] + l0.y + g0.y, 0.f);
    o[2] = fmaxf(acc[2] + l1.x + g0.z, 0.f);
    o[3] = fmaxf(acc[3] + l1.y + g0.w, 0.f);
    o[4] = fmaxf(acc[4] + l2.x + g1v.x, 0.f);
    o[5] = fmaxf(acc[5] + l2.y + g1v.y, 0.f);
    o[6] = fmaxf(acc[6] + l3.x + g1v.z, 0.f);
    o[7] = fmaxf(acc[7] + l3.y + g1v.w, 0.f);
    uint4 ov;
    *(__half2*)&ov.x = __floats2half2_rn(o[0], o[1]);
    *(__half2*)&ov.y = __floats2half2_rn(o[2], o[3]);
    *(__half2*)&ov.z = __floats2half2_rn(o[4], o[5]);
    *(__half2*)&ov.w = __floats2half2_rn(o[6], o[7]);
    *(uint4*)(d_h1h + (size_t)w * HCC + lane * 8) = ov;
}

__global__ void k_fold2(const float* __restrict__ g, const float* __restrict__ b,
                        const float* __restrict__ lin3W, const float* __restrict__ lin3b,
                        const float* __restrict__ g2W) {
    __shared__ float ssc[HCC], tsh[HCC];
    int tid = threadIdx.x;                    // 256
    float mu  = d_sum3[tid] * (1.f / NN);
    float var = d_sq3[tid] * (1.f / NN) - mu * mu;
    float sc  = rsqrtf(var + BN_EPS) * g[tid];
    ssc[tid] = sc;
    tsh[tid] = b[tid] - mu * sc;
    __syncthreads();
    #pragma unroll
    for (int j = 0; j < 4; j++) {
        float w = (j < 2) ? lin3W[tid * 2 + j] : g2W[tid * 2 + (j - 2)];
        d_W2effT[j * HCC + tid] = ssc[tid] * w;
    }
    if (tid < 4) {
        float acc = (tid < 2) ? lin3b[tid] : 0.f;
        for (int k = 0; k < HCC; k++) {
            float w = (tid < 2) ? lin3W[k * 2 + tid] : g2W[k * 2 + (tid - 2)];
            acc += tsh[k] * w;
        }
        d_c2[tid] = acc;
    }
}

// Y2 from fp16 h1 (lane covers 8 contiguous k)
__global__ void k_gemm2(const float* __restrict__ asrc, const float* __restrict__ adst) {
    __shared__ float Wsh[4 * HCC];
    int tid = threadIdx.x;
    for (int i = tid; i < 4 * HCC; i += blockDim.x) Wsh[i] = d_W2effT[i];
    __syncthreads();
    int w = (blockIdx.x * blockDim.x + tid) >> 5;
    int lane = tid & 31;
    if (w >= NN) return;
    uint4 pv = *(const uint4*)(d_h1h + (size_t)w * HCC + lane * 8);
    float hv[8];
    *(float2*)(hv)     = __half22float2(*(__half2*)&pv.x);
    *(float2*)(hv + 2) = __half22float2(*(__half2*)&pv.y);
    *(float2*)(hv + 4) = __half22float2(*(__half2*)&pv.z);
    *(float2*)(hv + 6) = __half22float2(*(__half2*)&pv.w);
    float a0 = 0.f, a1 = 0.f, a2 = 0.f, a3 = 0.f;
    #pragma unroll
    for (int j = 0; j < 8; j++) {
        int k = lane * 8 + j;
        a0 += hv[j] * Wsh[k];
        a1 += hv[j] * Wsh[HCC + k];
        a2 += hv[j] * Wsh[2 * HCC + k];
        a3 += hv[j] * Wsh[3 * HCC + k];
    }
    a0 = warpSum(a0); a1 = warpSum(a1); a2 = warpSum(a2); a3 = warpSum(a3);
    if (lane == 0) {
        a0 += d_c2[0]; a1 += d_c2[1]; a2 += d_c2[2]; a3 += d_c2[3];
        d_Y2[w * 4 + 0] = a0;
        d_Y2[w * 4 + 1] = a1;
        d_Y2[w * 4 + 2] = a2;
        d_Y2[w * 4 + 3] = a3;
        d_als2[w] = a2 * asrc[0] + a3 * asrc[1];
        d_ald2[w] = a2 * adst[0] + a3 * adst[1];
    }
}

__global__ void k_edge2(const float* __restrict__ g2bias, float* __restrict__ out) {
    int w = (blockIdx.x * blockDim.x + threadIdx.x) >> 5;
    int lane = threadIdx.x & 31;
    if (w >= NN) return;
    int beg = d_rowptr[w], end = d_rowptr[w + 1];
    float a0 = 0.f, a1 = 0.f;
    if (end > beg) {
        float ad = d_ald2[w];
        float ssum = 0.f;
        #pragma unroll 2
        for (int i = beg + lane; i < end; i += 32) {
            ssum += expl(lrelu(d_als2[d_ssrc[i]] + ad));
        }
        float inv = 1.f / (warpSum(ssum) + 1e-16f);
        #pragma unroll 2
        for (int i = beg + lane; i < end; i += 32) {
            int sv = d_ssrc[i];
            float wgt = expl(lrelu(d_als2[sv] + ad)) * inv;
            a0 += d_Y2[sv * 4 + 2] * wgt;
            a1 += d_Y2[sv * 4 + 3] * wgt;
        }
        a0 = warpSum(a0);
        a1 = warpSum(a1);
    }
    if (lane == 0) {
        float v0 = d_Y2[w * 4 + 0] + g2bias[0] + a0;
        float v1 = d_Y2[w * 4 + 1] + g2bias[1] + a1;
        out[w * 2 + 0] = v0 > 0.f ? v0 : 0.f;
        out[w * 2 + 1] = v1 > 0.f ? v1 : 0.f;
    }
}

// ---------------- launch ----------------
// Side stream + events for graph fork/join. Created lazily on the FIRST call
// (the uncaptured correctness run); recorded work is identical every call.
static cudaStream_t g_s1 = 0;
static cudaEvent_t  g_eFork = 0, g_eJoin = 0;

extern "C" void kernel_launch(void* const* d_in, const int* in_sizes, int n_in,
                              void* d_out, int out_size) {
    const float* x       = (const float*)d_in[0];
    const void*  ei      = (const void*)d_in[1];
    const float* bn1_g   = (const float*)d_in[2];
    const float* bn1_b   = (const float*)d_in[3];
    const float* bn3_g   = (const float*)d_in[4];
    const float* bn3_b   = (const float*)d_in[5];
    const float* lin1_W  = (const float*)d_in[6];
    const float* lin1_b  = (const float*)d_in[7];
    const float* lin3_W  = (const float*)d_in[8];
    const float* lin3_b  = (const float*)d_in[9];
    const float* g1_W    = (const float*)d_in[10];
    const float* g1_asrc = (const float*)d_in[11];
    const float* g1_adst = (const float*)d_in[12];
    const float* g1_bias = (const float*)d_in[13];
    const float* g2_W    = (const float*)d_in[14];
    const float* g2_asrc = (const float*)d_in[15];
    const float* g2_adst = (const float*)d_in[16];
    const float* g2_bias = (const float*)d_in[17];
    float* out = (float*)d_out;

    if (g_s1 == 0) {
        cudaStreamCreateWithFlags(&g_s1, cudaStreamNonBlocking);
        cudaEventCreateWithFlags(&g_eFork, cudaEventDisableTiming);
        cudaEventCreateWithFlags(&g_eJoin, cudaEventDisableTiming);
    }

    const int warpsGrid = (NN * 32 + 255) / 256;   // 6250 blocks (warp/node)

    // common init on main stream
    k_zero<<<(NN + 255) / 256, 256>>>();
    cudaEventRecord(g_eFork, 0);
    cudaStreamWaitEvent(g_s1, g_eFork, 0);

    // chain B (graph build) on side stream — overlaps with chain A
    k_detect<<<16, 256, 0, g_s1>>>((const long long*)ei);
    k_hist<<<784, 256, 0, g_s1>>>(ei);
    k_scan<<<1, 1024, 0, g_s1>>>();
    k_scatter<<<784, 256, 0, g_s1>>>(ei);
    cudaEventRecord(g_eJoin, g_s1);

    // chain A (dense compute) on main stream
    k_colstats_x<<<512, 256>>>(x);
    k_fold1<<<16, 512>>>(bn1_g, bn1_b, lin1_W, lin1_b, g1_W);
    dim3 g1grid(4, (NN + 127) / 128);
    k_gemm1<<<g1grid, 256>>>(x);
    k_alphas1<<<warpsGrid, 256>>>(g1_asrc, g1_adst);

    // join: edge1 needs CSR (chain B) + gemm1 outputs (chain A)
    cudaStreamWaitEvent(0, g_eJoin, 0);
    k_edge1<<<warpsGrid, 256>>>(g1_bias);
    k_colstats_h1<<<512, 256>>>();
    k_fold2<<<1, 256>>>(bn3_g, bn3_b, lin3_W, lin3_b, g2_W);
    k_gemm2<<<warpsGrid, 256>>>(g2_asrc, g2_adst);
    k_edge2<<<warpsGrid, 256>>>(g2_bias, out);
}